// round 10
// baseline (speedup 1.0000x reference)
#include <cuda_runtime.h>
#include <cuda_bf16.h>
#include <math.h>
#include <stdint.h>

#define B_     8
#define N_     1024
#define DIM_   512
#define H_     8
#define DH_    64
#define INNER_ 512
#define MROWS  (B_*N_)
#define SCALE_ 0.125f
#define EPS_   1e-12f
#define SD_STRIDE 1028

// Word permutation within 32-word (64 k-element) blocks:
//   natural o = ks*8 + s*4 + tig   ->   stored p = tig*8 + ks*2 + s
__device__ __forceinline__ int permw(int o)   { return (o&3)*8 + (o>>3)*2 + ((o>>2)&1); }
__device__ __forceinline__ int invperm(int w) { return ((w>>1)&3)*8 + (w&1)*4 + (w>>3); }

// ---------------- scratch -----------------------------------------------------
__device__ __align__(256) __nv_bfloat16 g_xhi[MROWS*DIM_],     g_xlo[MROWS*DIM_];
__device__ __align__(256) __nv_bfloat16 g_w1hi[3*INNER_*DIM_], g_w1lo[3*INNER_*DIM_];
__device__ __align__(256) __nv_bfloat16 g_w2hi[DIM_*INNER_],   g_w2lo[DIM_*INNER_];
__device__ __align__(256) __nv_bfloat16 g_qhi[B_*H_*N_*DH_],   g_qlo[B_*H_*N_*DH_];
__device__ __align__(256) __nv_bfloat16 g_khi[B_*H_*N_*DH_],   g_klo[B_*H_*N_*DH_];
__device__ __align__(256) __nv_bfloat16 g_vthi[B_*H_*DH_*N_],  g_vtlo[B_*H_*DH_*N_];
__device__ __align__(256) __nv_bfloat16 g_ahi[MROWS*INNER_],   g_alo[MROWS*INNER_];

// ---------------- helpers ------------------------------------------------------
__device__ __forceinline__ void mma_bf16(float* c, const uint32_t* a, uint32_t b0, uint32_t b1) {
    asm volatile("mma.sync.aligned.m16n8k16.row.col.f32.bf16.bf16.f32 "
        "{%0,%1,%2,%3}, {%4,%5,%6,%7}, {%8,%9}, {%0,%1,%2,%3};"
        : "+f"(c[0]), "+f"(c[1]), "+f"(c[2]), "+f"(c[3])
        : "r"(a[0]), "r"(a[1]), "r"(a[2]), "r"(a[3]), "r"(b0), "r"(b1));
}

__device__ __forceinline__ void split2(float x, float y, uint32_t& h, uint32_t& l) {
    uint32_t hh;
    asm("cvt.rn.bf16x2.f32 %0, %1, %2;" : "=r"(hh) : "f"(y), "f"(x));
    float hx = __uint_as_float(hh << 16);
    float hy = __uint_as_float(hh & 0xFFFF0000u);
    uint32_t ll;
    asm("cvt.rn.bf16x2.f32 %0, %1, %2;" : "=r"(ll) : "f"(y - hy), "f"(x - hx));
    h = hh; l = ll;
}
__device__ __forceinline__ void split1(float x, __nv_bfloat16& h, __nv_bfloat16& l) {
    h = __float2bfloat16_rn(x);
    l = __float2bfloat16_rn(x - __bfloat162float(h));
}
__device__ __forceinline__ uint32_t pack2(__nv_bfloat16 e0, __nv_bfloat16 e1) {
    return ((uint32_t)__bfloat16_as_ushort(e1) << 16) | __bfloat16_as_ushort(e0);
}

// ---------------- conversion kernels -------------------------------------------
__global__ void k_split_x(const float* __restrict__ in) {
    int row = blockIdx.x*8 + (threadIdx.x >> 5);
    int lane = threadIdx.x & 31;
    const float* src = in + (size_t)row*DIM_;
    uint32_t* dh = (uint32_t*)g_xhi + (size_t)row*256;
    uint32_t* dl = (uint32_t*)g_xlo + (size_t)row*256;
    #pragma unroll
    for (int j = 0; j < 8; j++) {
        int p = lane + 32*j;
        int o = (p & ~31) | invperm(p & 31);
        float2 v = *(const float2*)(src + 2*o);
        __nv_bfloat16 h0,l0,h1,l1; split1(v.x,h0,l0); split1(v.y,h1,l1);
        dh[p] = pack2(h0,h1);
        dl[p] = pack2(l0,l1);
    }
}

__global__ void k_split_w(const float* __restrict__ in, int W,
                          __nv_bfloat16* __restrict__ outh, __nv_bfloat16* __restrict__ outl) {
    __shared__ float s[64][33];
    int n0 = blockIdx.x*32, k0 = blockIdx.y*64;
    int t = threadIdx.x;
    int nn = t & 31, kk = t >> 5;
    #pragma unroll
    for (int i = 0; i < 8; i++)
        s[kk + 8*i][nn] = in[(size_t)(k0 + kk + 8*i)*W + n0 + nn];
    __syncthreads();
    int nl = t >> 3, wg = (t & 7)*4;
    uint32_t* oh = (uint32_t*)outh + (size_t)(n0+nl)*256 + blockIdx.y*32;
    uint32_t* ol = (uint32_t*)outl + (size_t)(n0+nl)*256 + blockIdx.y*32;
    #pragma unroll
    for (int j = 0; j < 4; j++) {
        int w = wg + j;
        int o = invperm(w);
        __nv_bfloat16 h0,l0,h1,l1;
        split1(s[2*o][nl],   h0, l0);
        split1(s[2*o+1][nl], h1, l1);
        oh[w] = pack2(h0,h1);
        ol[w] = pack2(l0,l1);
    }
}

// ---------------- warp GEMM core: 64x32 C tile, K=512, 32-k sub-chunks ----------
// Same 64x32 tile (R6/R8 traffic) but B-fragments live for only 2 k-steps at a
// time (32 regs vs 64) so 2 CTAs/SM fit under __launch_bounds__(256,2).
__device__ __forceinline__ void gemm_warp_64x32_s(
    const uint4* __restrict__ Ahi, const uint4* __restrict__ Alo,
    const uint4* __restrict__ Bhi, const uint4* __restrict__ Blo,
    int m_base, int n_base, int g, int tig, float c[4][4][4])
{
    #pragma unroll 2
    for (int hb = 0; hb < 16; hb++) {
        const int koff = (hb>>1)*8 + tig*2 + (hb&1);
        uint32_t bh[4][4], bl[4][4];
        #pragma unroll
        for (int nt = 0; nt < 4; nt++) {
            uint4 f = Bhi[(size_t)(n_base + nt*8 + g)*64 + koff];
            bh[nt][0]=f.x; bh[nt][1]=f.y; bh[nt][2]=f.z; bh[nt][3]=f.w;
            uint4 q = Blo[(size_t)(n_base + nt*8 + g)*64 + koff];
            bl[nt][0]=q.x; bl[nt][1]=q.y; bl[nt][2]=q.z; bl[nt][3]=q.w;
        }
        #pragma unroll
        for (int mt = 0; mt < 4; mt++) {
            const size_t ar = (size_t)(m_base + mt*16 + g)*64 + koff;
            uint4 F = Ahi[ar], S = Ahi[ar + 8*64];
            uint4 G = Alo[ar], T = Alo[ar + 8*64];
            uint32_t ah[2][4] = {{F.x,S.x,F.y,S.y},{F.z,S.z,F.w,S.w}};
            uint32_t al[2][4] = {{G.x,T.x,G.y,T.y},{G.z,T.z,G.w,T.w}};
            #pragma unroll
            for (int ks = 0; ks < 2; ks++)
                #pragma unroll
                for (int nt = 0; nt < 4; nt++) {
                    mma_bf16(c[mt][nt], ah[ks], bh[nt][ks*2], bh[nt][ks*2+1]);
                    mma_bf16(c[mt][nt], ah[ks], bl[nt][ks*2], bl[nt][ks*2+1]);
                    mma_bf16(c[mt][nt], al[ks], bh[nt][ks*2], bh[nt][ks*2+1]);
                }
        }
    }
}

// ---------------- kernel 1: qkv projection (2 CTA/SM) ---------------------------
__global__ void __launch_bounds__(256, 2) qkv_mma() {
    const int tid = threadIdx.x, w = tid >> 5, lane = tid & 31;
    const int g = lane >> 2, tig = lane & 3;
    const int m0 = blockIdx.y*128 + (w >> 2)*64;
    const int n0 = blockIdx.x*128 + (w & 3)*32;

    float c[4][4][4] = {};
    gemm_warp_64x32_s((const uint4*)g_xhi, (const uint4*)g_xlo,
                      (const uint4*)g_w1hi, (const uint4*)g_w1lo,
                      m0, n0, g, tig, c);

    #pragma unroll
    for (int mt = 0; mt < 4; mt++)
    #pragma unroll
    for (int nt = 0; nt < 4; nt++)
    #pragma unroll
    for (int half = 0; half < 2; half++) {
        int mg = m0 + mt*16 + g + half*8;
        int bb = mg >> 10, nn = mg & 1023;
        int ng = n0 + nt*8 + 2*tig;
        int sec = ng >> 9;
        int cc  = ng & 511;
        int hh  = cc >> 6, dd = cc & 63;
        float xv = c[mt][nt][half*2], yv = c[mt][nt][half*2+1];
        if (sec < 2) {
            uint32_t h, l; split2(xv, yv, h, l);
            int pw = permw(dd >> 1);
            size_t widx = (((size_t)bb*H_ + hh)*N_ + nn)*32 + pw;
            if (sec == 0) { ((uint32_t*)g_qhi)[widx] = h; ((uint32_t*)g_qlo)[widx] = l; }
            else          { ((uint32_t*)g_khi)[widx] = h; ((uint32_t*)g_klo)[widx] = l; }
        } else {
            __nv_bfloat16 h0,l0,h1,l1; split1(xv,h0,l0); split1(yv,h1,l1);
            int o = nn >> 1, hb = nn & 1;
            int pe = ((o & ~31) | permw(o & 31))*2 + hb;
            size_t base = (((size_t)bb*H_ + hh)*DH_ + dd)*N_;
            g_vthi[base + pe] = h0;       g_vtlo[base + pe] = l0;
            g_vthi[base + N_ + pe] = h1;  g_vtlo[base + N_ + pe] = l1;
        }
    }
}

// ---------------- kernel 2: fused attention (R8 version, unchanged) -------------
__global__ void __launch_bounds__(512) attn_mma(const float* __restrict__ spd,
                                                const float* __restrict__ head_mask) {
    extern __shared__ float sD[];
    float* sStat = sD + 32*SD_STRIDE;
    const int tid = threadIdx.x, w = tid >> 5, lane = tid & 31;
    const int g = lane >> 2, tig = lane & 3;
    const int bb = blockIdx.z, hh = blockIdx.y, row0 = blockIdx.x*32;
    const int mw = w & 1, nw = w >> 1;
    const int mrow = mw*16 + g;

    if (tid < 64) sStat[tid] = 0.f;
    __syncthreads();

    const uint4* Khi4 = (const uint4*)g_khi + (size_t)(bb*H_+hh)*N_*8;
    const uint4* Klo4 = (const uint4*)g_klo + (size_t)(bb*H_+hh)*N_*8;

    uint32_t ah[4][4], al[4][4];
    {
        const uint4* qh = (const uint4*)g_qhi + ((size_t)(bb*H_+hh)*N_ + row0 + mrow)*8 + tig*2;
        const uint4* ql = (const uint4*)g_qlo + ((size_t)(bb*H_+hh)*N_ + row0 + mrow)*8 + tig*2;
        uint4 F0 = qh[0],    F1 = qh[1];
        uint4 S0 = qh[8*8],  S1 = qh[8*8+1];
        uint4 G0 = ql[0],    G1 = ql[1];
        uint4 T0 = ql[8*8],  T1 = ql[8*8+1];
        ah[0][0]=F0.x; ah[0][1]=S0.x; ah[0][2]=F0.y; ah[0][3]=S0.y;
        ah[1][0]=F0.z; ah[1][1]=S0.z; ah[1][2]=F0.w; ah[1][3]=S0.w;
        ah[2][0]=F1.x; ah[2][1]=S1.x; ah[2][2]=F1.y; ah[2][3]=S1.y;
        ah[3][0]=F1.z; ah[3][1]=S1.z; ah[3][2]=F1.w; ah[3][3]=S1.w;
        al[0][0]=G0.x; al[0][1]=T0.x; al[0][2]=G0.y; al[0][3]=T0.y;
        al[1][0]=G0.z; al[1][1]=T0.z; al[1][2]=G0.w; al[1][3]=T0.w;
        al[2][0]=G1.x; al[2][1]=T1.x; al[2][2]=G1.y; al[2][3]=T1.y;
        al[3][0]=G1.z; al[3][1]=T1.z; al[3][2]=G1.w; al[3][3]=T1.w;
    }
    const float* sp0 = spd + ((size_t)bb*N_ + row0 + mrow)*N_;
    const float* sp1 = sp0 + 8*N_;
    float d2a = 0.f, p2a = 0.f, d2b = 0.f, p2b = 0.f;

    #pragma unroll 2
    for (int nt = 0; nt < 16; nt++) {
        const int n0 = nw*128 + nt*8;
        const uint4* ph = Khi4 + (size_t)(n0+g)*8 + tig*2;
        const uint4* pl = Klo4 + (size_t)(n0+g)*8 + tig*2;
        uint4 F0 = ph[0], F1 = ph[1];
        uint4 G0 = pl[0], G1 = pl[1];
        uint32_t bhw[8] = {F0.x,F0.y,F0.z,F0.w,F1.x,F1.y,F1.z,F1.w};
        uint32_t blw[8] = {G0.x,G0.y,G0.z,G0.w,G1.x,G1.y,G1.z,G1.w};
        float c[4] = {0.f,0.f,0.f,0.f};
        #pragma unroll
        for (int ks = 0; ks < 4; ks++) {
            mma_bf16(c, ah[ks], bhw[ks*2], bhw[ks*2+1]);
            mma_bf16(c, ah[ks], blw[ks*2], blw[ks*2+1]);
            mma_bf16(c, al[ks], bhw[ks*2], bhw[ks*2+1]);
        }
        float2 v0 = { c[0]*SCALE_, c[1]*SCALE_ };
        float2 v1 = { c[2]*SCALE_, c[3]*SCALE_ };
        *(float2*)&sD[(size_t)mrow*SD_STRIDE + n0 + 2*tig]     = v0;
        *(float2*)&sD[(size_t)(mrow+8)*SD_STRIDE + n0 + 2*tig] = v1;
        float2 s0 = *(const float2*)&sp0[n0 + 2*tig];
        float2 s1 = *(const float2*)&sp1[n0 + 2*tig];
        d2a += v0.x*v0.x + v0.y*v0.y;
        p2a += (v0.x*s0.x)*(v0.x*s0.x) + (v0.y*s0.y)*(v0.y*s0.y);
        d2b += v1.x*v1.x + v1.y*v1.y;
        p2b += (v1.x*s1.x)*(v1.x*s1.x) + (v1.y*s1.y)*(v1.y*s1.y);
    }
    #pragma unroll
    for (int o = 1; o <= 2; o <<= 1) {
        d2a += __shfl_xor_sync(0xffffffffu, d2a, o);
        p2a += __shfl_xor_sync(0xffffffffu, p2a, o);
        d2b += __shfl_xor_sync(0xffffffffu, d2b, o);
        p2b += __shfl_xor_sync(0xffffffffu, p2b, o);
    }
    if      (tig == 0) atomicAdd(&sStat[mrow*2 + 0],     d2a);
    else if (tig == 1) atomicAdd(&sStat[mrow*2 + 1],     p2a);
    else if (tig == 2) atomicAdd(&sStat[(mrow+8)*2 + 0], d2b);
    else               atomicAdd(&sStat[(mrow+8)*2 + 1], p2b);
    __syncthreads();

    float msum = 0.f;
    #pragma unroll
    for (int i = 0; i < H_; i++) msum += head_mask[i];
    const float scale_m = head_mask[hh] * (float)H_ / msum;
    const int pl = permw(lane);

    #pragma unroll
    for (int rr = 0; rr < 2; rr++) {
        const int r = w*2 + rr, rg = row0 + r;
        float* drow = sD + (size_t)r*SD_STRIDE;
        const float* srow = spd + ((size_t)bb*N_ + rg)*N_;
        const float rnorm = sqrtf(sStat[2*r]) / fmaxf(sqrtf(sStat[2*r+1]), EPS_);

        float vb[32];
        float s = 0.f;
        #pragma unroll
        for (int i = 0; i < 16; i++) {
            float2 dp = *(const float2*)&drow[2*lane + 64*i];
            float2 sp = *(const float2*)&srow[2*lane + 64*i];
            float e0 = __expf(fmaf(dp.x*sp.x, rnorm, dp.x));
            float e1 = __expf(fmaf(dp.y*sp.y, rnorm, dp.y));
            vb[2*i] = e0; vb[2*i+1] = e1;
            s += e0 + e1;
        }
        #pragma unroll
        for (int o = 16; o > 0; o >>= 1) s += __shfl_xor_sync(0xffffffffu, s, o);
        const float inv = scale_m / s;

        uint32_t* dw = (uint32_t*)drow;
        #pragma unroll
        for (int i = 0; i < 16; i++) {
            uint32_t h, l; split2(vb[2*i]*inv, vb[2*i+1]*inv, h, l);
            dw[i*32 + pl]       = h;
            dw[512 + i*32 + pl] = l;
        }
    }
    __syncthreads();

    const uint4* Vhi4 = (const uint4*)g_vthi + (size_t)(bb*H_+hh)*DH_*128;
    const uint4* Vlo4 = (const uint4*)g_vtlo + (size_t)(bb*H_+hh)*DH_*128;
    const int dh0 = nw*8;
    float oc[4] = {0.f,0.f,0.f,0.f};
    const uint4* r0 = (const uint4*)(sD + (size_t)mrow*SD_STRIDE);
    const uint4* r1 = (const uint4*)(sD + (size_t)(mrow+8)*SD_STRIDE);

    #pragma unroll 2
    for (int kb = 0; kb < 16; kb++) {
        const int ob = kb*8 + tig*2;
        uint4 F0 = r0[ob],       F1 = r0[ob+1];
        uint4 H0 = r1[ob],       H1 = r1[ob+1];
        uint4 G0 = r0[128+ob],   G1 = r0[128+ob+1];
        uint4 T0 = r1[128+ob],   T1 = r1[128+ob+1];
        uint32_t a4h[4][4] = {
            {F0.x,H0.x,F0.y,H0.y},{F0.z,H0.z,F0.w,H0.w},
            {F1.x,H1.x,F1.y,H1.y},{F1.z,H1.z,F1.w,H1.w}};
        uint32_t a4l[4][4] = {
            {G0.x,T0.x,G0.y,T0.y},{G0.z,T0.z,G0.w,T0.w},
            {G1.x,T1.x,G1.y,T1.y},{G1.z,T1.z,G1.w,T1.w}};
        const uint4* ph = Vhi4 + (size_t)(dh0 + g)*128 + ob;
        const uint4* pv = Vlo4 + (size_t)(dh0 + g)*128 + ob;
        uint4 P0 = ph[0], P1 = ph[1];
        uint4 Q0 = pv[0], Q1 = pv[1];
        uint32_t bhw[8] = {P0.x,P0.y,P0.z,P0.w,P1.x,P1.y,P1.z,P1.w};
        uint32_t blw[8] = {Q0.x,Q0.y,Q0.z,Q0.w,Q1.x,Q1.y,Q1.z,Q1.w};
        #pragma unroll
        for (int ks = 0; ks < 4; ks++) {
            mma_bf16(oc, a4h[ks], bhw[ks*2], bhw[ks*2+1]);
            mma_bf16(oc, a4h[ks], blw[ks*2], blw[ks*2+1]);
            mma_bf16(oc, a4l[ks], bhw[ks*2], bhw[ks*2+1]);
        }
    }

    #pragma unroll
    for (int half = 0; half < 2; half++) {
        int rg  = row0 + mw*16 + g + half*8;
        size_t mg = (size_t)bb*N_ + rg;
        int rcol = dh0 + 2*tig;
        uint32_t h, l; split2(oc[half*2], oc[half*2+1], h, l);
        int pw = hh*32 + permw(rcol >> 1);
        size_t widx = mg*256 + pw;
        ((uint32_t*)g_ahi)[widx] = h; ((uint32_t*)g_alo)[widx] = l;
    }
}

// ---------------- kernel 3: output projection (2 CTA/SM) ------------------------
__global__ void __launch_bounds__(256, 2) out_mma(const float* __restrict__ bout,
                                                  float* __restrict__ out) {
    const int tid = threadIdx.x, w = tid >> 5, lane = tid & 31;
    const int g = lane >> 2, tig = lane & 3;
    const int m0 = blockIdx.y*128 + (w >> 2)*64;
    const int n0 = blockIdx.x*128 + (w & 3)*32;

    float c[4][4][4] = {};
    gemm_warp_64x32_s((const uint4*)g_ahi, (const uint4*)g_alo,
                      (const uint4*)g_w2hi, (const uint4*)g_w2lo,
                      m0, n0, g, tig, c);

    #pragma unroll
    for (int mt = 0; mt < 4; mt++)
    #pragma unroll
    for (int nt = 0; nt < 4; nt++)
    #pragma unroll
    for (int half = 0; half < 2; half++) {
        int mg = m0 + mt*16 + g + half*8;
        int ng = n0 + nt*8 + 2*tig;
        float2 v = { c[mt][nt][half*2]   + bout[ng],
                     c[mt][nt][half*2+1] + bout[ng+1] };
        *(float2*)(out + (size_t)mg*DIM_ + ng) = v;
    }
}

// ---------------- launch ---------------------------------------------------------
extern "C" void kernel_launch(void* const* d_in, const int* in_sizes, int n_in,
                              void* d_out, int out_size) {
    const float* x         = (const float*)d_in[0];
    const float* spd       = (const float*)d_in[1];
    const float* head_mask = (const float*)d_in[2];
    const float* W_qkv     = (const float*)d_in[3];
    const float* W_out     = (const float*)d_in[4];
    const float* b_out     = (const float*)d_in[5];
    float* out = (float*)d_out;

    __nv_bfloat16 *w1h, *w1l, *w2h, *w2l;
    cudaGetSymbolAddress((void**)&w1h, g_w1hi); cudaGetSymbolAddress((void**)&w1l, g_w1lo);
    cudaGetSymbolAddress((void**)&w2h, g_w2hi); cudaGetSymbolAddress((void**)&w2l, g_w2lo);

    k_split_x<<<MROWS/8, 256>>>(x);
    k_split_w<<<dim3(48, 8), 256>>>(W_qkv, 3*INNER_, w1h, w1l);
    k_split_w<<<dim3(16, 8), 256>>>(W_out, DIM_,     w2h, w2l);

    qkv_mma<<<dim3(12, 64), 256>>>();

    size_t smem = (size_t)(32*SD_STRIDE + 64)*sizeof(float);
    cudaFuncSetAttribute(attn_mma, cudaFuncAttributeMaxDynamicSharedMemorySize, (int)smem);
    attn_mma<<<dim3(N_/32, H_, B_), 512, smem>>>(spd, head_mask);

    out_mma<<<dim3(4, 64), 256>>>(b_out, out);
}

// round 12
// speedup vs baseline: 1.0599x; 1.0599x over previous
#include <cuda_runtime.h>
#include <cuda_bf16.h>
#include <math.h>
#include <stdint.h>

#define B_     8
#define N_     1024
#define DIM_   512
#define H_     8
#define DH_    64
#define INNER_ 512
#define MROWS  (B_*N_)
#define SCALE_ 0.125f
#define EPS_   1e-12f
#define SD_STRIDE 1028

// Word permutation within 32-word (64 k-element) blocks:
//   natural o = ks*8 + s*4 + tig   ->   stored p = tig*8 + ks*2 + s
__device__ __forceinline__ int permw(int o)   { return (o&3)*8 + (o>>3)*2 + ((o>>2)&1); }
__device__ __forceinline__ int invperm(int w) { return ((w>>1)&3)*8 + (w&1)*4 + (w>>3); }

// ---------------- scratch -----------------------------------------------------
__device__ __align__(256) __nv_bfloat16 g_xhi[MROWS*DIM_],     g_xlo[MROWS*DIM_];
__device__ __align__(256) __nv_bfloat16 g_w1hi[3*INNER_*DIM_], g_w1lo[3*INNER_*DIM_];
__device__ __align__(256) __nv_bfloat16 g_w2hi[DIM_*INNER_],   g_w2lo[DIM_*INNER_];
__device__ __align__(256) __nv_bfloat16 g_qhi[B_*H_*N_*DH_],   g_qlo[B_*H_*N_*DH_];
__device__ __align__(256) __nv_bfloat16 g_khi[B_*H_*N_*DH_],   g_klo[B_*H_*N_*DH_];
__device__ __align__(256) __nv_bfloat16 g_vthi[B_*H_*DH_*N_],  g_vtlo[B_*H_*DH_*N_];
__device__ __align__(256) __nv_bfloat16 g_ahi[MROWS*INNER_],   g_alo[MROWS*INNER_];

// ---------------- helpers ------------------------------------------------------
__device__ __forceinline__ void mma_bf16(float* c, const uint32_t* a, uint32_t b0, uint32_t b1) {
    asm volatile("mma.sync.aligned.m16n8k16.row.col.f32.bf16.bf16.f32 "
        "{%0,%1,%2,%3}, {%4,%5,%6,%7}, {%8,%9}, {%0,%1,%2,%3};"
        : "+f"(c[0]), "+f"(c[1]), "+f"(c[2]), "+f"(c[3])
        : "r"(a[0]), "r"(a[1]), "r"(a[2]), "r"(a[3]), "r"(b0), "r"(b1));
}

__device__ __forceinline__ void split2(float x, float y, uint32_t& h, uint32_t& l) {
    uint32_t hh;
    asm("cvt.rn.bf16x2.f32 %0, %1, %2;" : "=r"(hh) : "f"(y), "f"(x));
    float hx = __uint_as_float(hh << 16);
    float hy = __uint_as_float(hh & 0xFFFF0000u);
    uint32_t ll;
    asm("cvt.rn.bf16x2.f32 %0, %1, %2;" : "=r"(ll) : "f"(y - hy), "f"(x - hx));
    h = hh; l = ll;
}
__device__ __forceinline__ void split1(float x, __nv_bfloat16& h, __nv_bfloat16& l) {
    h = __float2bfloat16_rn(x);
    l = __float2bfloat16_rn(x - __bfloat162float(h));
}
__device__ __forceinline__ uint32_t pack2(__nv_bfloat16 e0, __nv_bfloat16 e1) {
    return ((uint32_t)__bfloat16_as_ushort(e1) << 16) | __bfloat16_as_ushort(e0);
}

// ---------------- conversion kernels -------------------------------------------
__global__ void k_split_x(const float* __restrict__ in) {
    int row = blockIdx.x*8 + (threadIdx.x >> 5);
    int lane = threadIdx.x & 31;
    const float* src = in + (size_t)row*DIM_;
    uint32_t* dh = (uint32_t*)g_xhi + (size_t)row*256;
    uint32_t* dl = (uint32_t*)g_xlo + (size_t)row*256;
    #pragma unroll
    for (int j = 0; j < 8; j++) {
        int p = lane + 32*j;
        int o = (p & ~31) | invperm(p & 31);
        float2 v = *(const float2*)(src + 2*o);
        __nv_bfloat16 h0,l0,h1,l1; split1(v.x,h0,l0); split1(v.y,h1,l1);
        dh[p] = pack2(h0,h1);
        dl[p] = pack2(l0,l1);
    }
}

__global__ void k_split_w(const float* __restrict__ in, int W,
                          __nv_bfloat16* __restrict__ outh, __nv_bfloat16* __restrict__ outl) {
    __shared__ float s[64][33];
    int n0 = blockIdx.x*32, k0 = blockIdx.y*64;
    int t = threadIdx.x;
    int nn = t & 31, kk = t >> 5;
    #pragma unroll
    for (int i = 0; i < 8; i++)
        s[kk + 8*i][nn] = in[(size_t)(k0 + kk + 8*i)*W + n0 + nn];
    __syncthreads();
    int nl = t >> 3, wg = (t & 7)*4;
    uint32_t* oh = (uint32_t*)outh + (size_t)(n0+nl)*256 + blockIdx.y*32;
    uint32_t* ol = (uint32_t*)outl + (size_t)(n0+nl)*256 + blockIdx.y*32;
    #pragma unroll
    for (int j = 0; j < 4; j++) {
        int w = wg + j;
        int o = invperm(w);
        __nv_bfloat16 h0,l0,h1,l1;
        split1(s[2*o][nl],   h0, l0);
        split1(s[2*o+1][nl], h1, l1);
        oh[w] = pack2(h0,h1);
        ol[w] = pack2(l0,l1);
    }
}

// ---------------- warp GEMM core: 64x32 C tile, K=512 (R6/R8 config) ------------
__device__ __forceinline__ void gemm_warp_64x32_p(
    const uint4* __restrict__ Ahi, const uint4* __restrict__ Alo,
    const uint4* __restrict__ Bhi, const uint4* __restrict__ Blo,
    int m_base, int n_base, int g, int tig, float c[4][4][4])
{
    for (int kb = 0; kb < 8; kb++) {
        uint32_t bh[4][8], bl[4][8];
        #pragma unroll
        for (int nt = 0; nt < 4; nt++) {
            const uint4* p = Bhi + (size_t)(n_base + nt*8 + g)*64 + kb*8 + tig*2;
            uint4 f0 = p[0], f1 = p[1];
            bh[nt][0]=f0.x; bh[nt][1]=f0.y; bh[nt][2]=f0.z; bh[nt][3]=f0.w;
            bh[nt][4]=f1.x; bh[nt][5]=f1.y; bh[nt][6]=f1.z; bh[nt][7]=f1.w;
            const uint4* q = Blo + (size_t)(n_base + nt*8 + g)*64 + kb*8 + tig*2;
            uint4 g0 = q[0], g1 = q[1];
            bl[nt][0]=g0.x; bl[nt][1]=g0.y; bl[nt][2]=g0.z; bl[nt][3]=g0.w;
            bl[nt][4]=g1.x; bl[nt][5]=g1.y; bl[nt][6]=g1.z; bl[nt][7]=g1.w;
        }
        #pragma unroll
        for (int mt = 0; mt < 4; mt++) {
            const uint4* pr = Ahi + (size_t)(m_base + mt*16 + g)*64 + kb*8 + tig*2;
            uint4 F0 = pr[0],     F1 = pr[1];
            uint4 S0 = pr[8*64],  S1 = pr[8*64 + 1];
            const uint4* ql = Alo + (size_t)(m_base + mt*16 + g)*64 + kb*8 + tig*2;
            uint4 G0 = ql[0],     G1 = ql[1];
            uint4 T0 = ql[8*64],  T1 = ql[8*64 + 1];
            uint32_t ah[4][4] = {
                {F0.x,S0.x,F0.y,S0.y},{F0.z,S0.z,F0.w,S0.w},
                {F1.x,S1.x,F1.y,S1.y},{F1.z,S1.z,F1.w,S1.w}};
            uint32_t al[4][4] = {
                {G0.x,T0.x,G0.y,T0.y},{G0.z,T0.z,G0.w,T0.w},
                {G1.x,T1.x,G1.y,T1.y},{G1.z,T1.z,G1.w,T1.w}};
            #pragma unroll
            for (int ks = 0; ks < 4; ks++)
                #pragma unroll
                for (int nt = 0; nt < 4; nt++) {
                    mma_bf16(c[mt][nt], ah[ks], bh[nt][ks*2], bh[nt][ks*2+1]);
                    mma_bf16(c[mt][nt], ah[ks], bl[nt][ks*2], bl[nt][ks*2+1]);
                    mma_bf16(c[mt][nt], al[ks], bh[nt][ks*2], bh[nt][ks*2+1]);
                }
        }
    }
}

// ---------------- kernel 1: qkv projection (R8 config) --------------------------
__global__ void __launch_bounds__(256) qkv_mma() {
    const int tid = threadIdx.x, w = tid >> 5, lane = tid & 31;
    const int g = lane >> 2, tig = lane & 3;
    const int m0 = blockIdx.y*128 + (w >> 2)*64;
    const int n0 = blockIdx.x*128 + (w & 3)*32;

    float c[4][4][4] = {};
    gemm_warp_64x32_p((const uint4*)g_xhi, (const uint4*)g_xlo,
                      (const uint4*)g_w1hi, (const uint4*)g_w1lo,
                      m0, n0, g, tig, c);

    #pragma unroll
    for (int mt = 0; mt < 4; mt++)
    #pragma unroll
    for (int nt = 0; nt < 4; nt++)
    #pragma unroll
    for (int half = 0; half < 2; half++) {
        int mg = m0 + mt*16 + g + half*8;
        int bb = mg >> 10, nn = mg & 1023;
        int ng = n0 + nt*8 + 2*tig;
        int sec = ng >> 9;
        int cc  = ng & 511;
        int hh  = cc >> 6, dd = cc & 63;
        float xv = c[mt][nt][half*2], yv = c[mt][nt][half*2+1];
        if (sec < 2) {
            uint32_t h, l; split2(xv, yv, h, l);
            int pw = permw(dd >> 1);
            size_t widx = (((size_t)bb*H_ + hh)*N_ + nn)*32 + pw;
            if (sec == 0) { ((uint32_t*)g_qhi)[widx] = h; ((uint32_t*)g_qlo)[widx] = l; }
            else          { ((uint32_t*)g_khi)[widx] = h; ((uint32_t*)g_klo)[widx] = l; }
        } else {
            __nv_bfloat16 h0,l0,h1,l1; split1(xv,h0,l0); split1(yv,h1,l1);
            int o = nn >> 1, hb = nn & 1;
            int pe = ((o & ~31) | permw(o & 31))*2 + hb;
            size_t base = (((size_t)bb*H_ + hh)*DH_ + dd)*N_;
            g_vthi[base + pe] = h0;       g_vtlo[base + pe] = l0;
            g_vthi[base + N_ + pe] = h1;  g_vtlo[base + N_ + pe] = l1;
        }
    }
}

// ---------------- kernel 2: fused attention (3-way split accumulators) ----------
__global__ void __launch_bounds__(512) attn_mma(const float* __restrict__ spd,
                                                const float* __restrict__ head_mask) {
    extern __shared__ float sD[];
    float* sStat = sD + 32*SD_STRIDE;
    const int tid = threadIdx.x, w = tid >> 5, lane = tid & 31;
    const int g = lane >> 2, tig = lane & 3;
    const int bb = blockIdx.z, hh = blockIdx.y, row0 = blockIdx.x*32;
    const int mw = w & 1, nw = w >> 1;
    const int mrow = mw*16 + g;

    if (tid < 64) sStat[tid] = 0.f;
    __syncthreads();

    const uint4* Khi4 = (const uint4*)g_khi + (size_t)(bb*H_+hh)*N_*8;
    const uint4* Klo4 = (const uint4*)g_klo + (size_t)(bb*H_+hh)*N_*8;

    // ---- phase 1: dots = (Q K^T) * SCALE into sD + fused norm partials ----
    uint32_t ah[4][4], al[4][4];
    {
        const uint4* qh = (const uint4*)g_qhi + ((size_t)(bb*H_+hh)*N_ + row0 + mrow)*8 + tig*2;
        const uint4* ql = (const uint4*)g_qlo + ((size_t)(bb*H_+hh)*N_ + row0 + mrow)*8 + tig*2;
        uint4 F0 = qh[0],    F1 = qh[1];
        uint4 S0 = qh[8*8],  S1 = qh[8*8+1];
        uint4 G0 = ql[0],    G1 = ql[1];
        uint4 T0 = ql[8*8],  T1 = ql[8*8+1];
        ah[0][0]=F0.x; ah[0][1]=S0.x; ah[0][2]=F0.y; ah[0][3]=S0.y;
        ah[1][0]=F0.z; ah[1][1]=S0.z; ah[1][2]=F0.w; ah[1][3]=S0.w;
        ah[2][0]=F1.x; ah[2][1]=S1.x; ah[2][2]=F1.y; ah[2][3]=S1.y;
        ah[3][0]=F1.z; ah[3][1]=S1.z; ah[3][2]=F1.w; ah[3][3]=S1.w;
        al[0][0]=G0.x; al[0][1]=T0.x; al[0][2]=G0.y; al[0][3]=T0.y;
        al[1][0]=G0.z; al[1][1]=T0.z; al[1][2]=G0.w; al[1][3]=T0.w;
        al[2][0]=G1.x; al[2][1]=T1.x; al[2][2]=G1.y; al[2][3]=T1.y;
        al[3][0]=G1.z; al[3][1]=T1.z; al[3][2]=G1.w; al[3][3]=T1.w;
    }
    const float* sp0 = spd + ((size_t)bb*N_ + row0 + mrow)*N_;
    const float* sp1 = sp0 + 8*N_;
    float d2a = 0.f, p2a = 0.f, d2b = 0.f, p2b = 0.f;

    #pragma unroll 2
    for (int nt = 0; nt < 16; nt++) {
        const int n0 = nw*128 + nt*8;
        const uint4* ph = Khi4 + (size_t)(n0+g)*8 + tig*2;
        const uint4* pl = Klo4 + (size_t)(n0+g)*8 + tig*2;
        uint4 F0 = ph[0], F1 = ph[1];
        uint4 G0 = pl[0], G1 = pl[1];
        uint32_t bhw[8] = {F0.x,F0.y,F0.z,F0.w,F1.x,F1.y,F1.z,F1.w};
        uint32_t blw[8] = {G0.x,G0.y,G0.z,G0.w,G1.x,G1.y,G1.z,G1.w};
        // 3 independent accumulator chains (hi*hi, hi*lo, lo*hi)
        float chh[4] = {0.f,0.f,0.f,0.f};
        float chl[4] = {0.f,0.f,0.f,0.f};
        float clh[4] = {0.f,0.f,0.f,0.f};
        #pragma unroll
        for (int ks = 0; ks < 4; ks++) {
            mma_bf16(chh, ah[ks], bhw[ks*2], bhw[ks*2+1]);
            mma_bf16(chl, ah[ks], blw[ks*2], blw[ks*2+1]);
            mma_bf16(clh, al[ks], bhw[ks*2], bhw[ks*2+1]);
        }
        float c0 = chh[0] + chl[0] + clh[0];
        float c1 = chh[1] + chl[1] + clh[1];
        float c2 = chh[2] + chl[2] + clh[2];
        float c3 = chh[3] + chl[3] + clh[3];
        float2 v0 = { c0*SCALE_, c1*SCALE_ };
        float2 v1 = { c2*SCALE_, c3*SCALE_ };
        *(float2*)&sD[(size_t)mrow*SD_STRIDE + n0 + 2*tig]     = v0;
        *(float2*)&sD[(size_t)(mrow+8)*SD_STRIDE + n0 + 2*tig] = v1;
        float2 s0 = *(const float2*)&sp0[n0 + 2*tig];
        float2 s1 = *(const float2*)&sp1[n0 + 2*tig];
        d2a += v0.x*v0.x + v0.y*v0.y;
        p2a += (v0.x*s0.x)*(v0.x*s0.x) + (v0.y*s0.y)*(v0.y*s0.y);
        d2b += v1.x*v1.x + v1.y*v1.y;
        p2b += (v1.x*s1.x)*(v1.x*s1.x) + (v1.y*s1.y)*(v1.y*s1.y);
    }
    #pragma unroll
    for (int o = 1; o <= 2; o <<= 1) {
        d2a += __shfl_xor_sync(0xffffffffu, d2a, o);
        p2a += __shfl_xor_sync(0xffffffffu, p2a, o);
        d2b += __shfl_xor_sync(0xffffffffu, d2b, o);
        p2b += __shfl_xor_sync(0xffffffffu, p2b, o);
    }
    if      (tig == 0) atomicAdd(&sStat[mrow*2 + 0],     d2a);
    else if (tig == 1) atomicAdd(&sStat[mrow*2 + 1],     p2a);
    else if (tig == 2) atomicAdd(&sStat[(mrow+8)*2 + 0], d2b);
    else               atomicAdd(&sStat[(mrow+8)*2 + 1], p2b);
    __syncthreads();

    // ---- phase 2: single pass: exp (no max-sub) in regs, sum, repack bf16 ----
    float msum = 0.f;
    #pragma unroll
    for (int i = 0; i < H_; i++) msum += head_mask[i];
    const float scale_m = head_mask[hh] * (float)H_ / msum;
    const int pl = permw(lane);

    #pragma unroll
    for (int rr = 0; rr < 2; rr++) {
        const int r = w*2 + rr, rg = row0 + r;
        float* drow = sD + (size_t)r*SD_STRIDE;
        const float* srow = spd + ((size_t)bb*N_ + rg)*N_;
        const float rnorm = sqrtf(sStat[2*r]) / fmaxf(sqrtf(sStat[2*r+1]), EPS_);

        float vb[32];
        float s = 0.f;
        #pragma unroll
        for (int i = 0; i < 16; i++) {
            float2 dp = *(const float2*)&drow[2*lane + 64*i];
            float2 sp = *(const float2*)&srow[2*lane + 64*i];
            float e0 = __expf(fmaf(dp.x*sp.x, rnorm, dp.x));
            float e1 = __expf(fmaf(dp.y*sp.y, rnorm, dp.y));
            vb[2*i] = e0; vb[2*i+1] = e1;
            s += e0 + e1;
        }
        #pragma unroll
        for (int o = 16; o > 0; o >>= 1) s += __shfl_xor_sync(0xffffffffu, s, o);
        const float inv = scale_m / s;

        uint32_t* dw = (uint32_t*)drow;
        #pragma unroll
        for (int i = 0; i < 16; i++) {
            uint32_t h, l; split2(vb[2*i]*inv, vb[2*i+1]*inv, h, l);
            dw[i*32 + pl]       = h;
            dw[512 + i*32 + pl] = l;
        }
    }
    __syncthreads();

    // ---- phase 3: O = attn @ V (3 independent accumulator chains) ----
    const uint4* Vhi4 = (const uint4*)g_vthi + (size_t)(bb*H_+hh)*DH_*128;
    const uint4* Vlo4 = (const uint4*)g_vtlo + (size_t)(bb*H_+hh)*DH_*128;
    const int dh0 = nw*8;
    float ohh[4] = {0.f,0.f,0.f,0.f};
    float ohl[4] = {0.f,0.f,0.f,0.f};
    float olh[4] = {0.f,0.f,0.f,0.f};
    const uint4* r0 = (const uint4*)(sD + (size_t)mrow*SD_STRIDE);
    const uint4* r1 = (const uint4*)(sD + (size_t)(mrow+8)*SD_STRIDE);

    #pragma unroll 2
    for (int kb = 0; kb < 16; kb++) {
        const int ob = kb*8 + tig*2;
        uint4 F0 = r0[ob],       F1 = r0[ob+1];
        uint4 H0 = r1[ob],       H1 = r1[ob+1];
        uint4 G0 = r0[128+ob],   G1 = r0[128+ob+1];
        uint4 T0 = r1[128+ob],   T1 = r1[128+ob+1];
        uint32_t a4h[4][4] = {
            {F0.x,H0.x,F0.y,H0.y},{F0.z,H0.z,F0.w,H0.w},
            {F1.x,H1.x,F1.y,H1.y},{F1.z,H1.z,F1.w,H1.w}};
        uint32_t a4l[4][4] = {
            {G0.x,T0.x,G0.y,T0.y},{G0.z,T0.z,G0.w,T0.w},
            {G1.x,T1.x,G1.y,T1.y},{G1.z,T1.z,G1.w,T1.w}};
        const uint4* ph = Vhi4 + (size_t)(dh0 + g)*128 + ob;
        const uint4* pv = Vlo4 + (size_t)(dh0 + g)*128 + ob;
        uint4 P0 = ph[0], P1 = ph[1];
        uint4 Q0 = pv[0], Q1 = pv[1];
        uint32_t bhw[8] = {P0.x,P0.y,P0.z,P0.w,P1.x,P1.y,P1.z,P1.w};
        uint32_t blw[8] = {Q0.x,Q0.y,Q0.z,Q0.w,Q1.x,Q1.y,Q1.z,Q1.w};
        #pragma unroll
        for (int ks = 0; ks < 4; ks++) {
            mma_bf16(ohh, a4h[ks], bhw[ks*2], bhw[ks*2+1]);
            mma_bf16(ohl, a4h[ks], blw[ks*2], blw[ks*2+1]);
            mma_bf16(olh, a4l[ks], bhw[ks*2], bhw[ks*2+1]);
        }
    }

    #pragma unroll
    for (int half = 0; half < 2; half++) {
        int rg  = row0 + mw*16 + g + half*8;
        size_t mg = (size_t)bb*N_ + rg;
        int rcol = dh0 + 2*tig;
        float x0 = ohh[half*2]   + ohl[half*2]   + olh[half*2];
        float y0 = ohh[half*2+1] + ohl[half*2+1] + olh[half*2+1];
        uint32_t h, l; split2(x0, y0, h, l);
        int pw = hh*32 + permw(rcol >> 1);
        size_t widx = mg*256 + pw;
        ((uint32_t*)g_ahi)[widx] = h; ((uint32_t*)g_alo)[widx] = l;
    }
}

// ---------------- kernel 3: output projection (R8 config) -----------------------
__global__ void __launch_bounds__(256) out_mma(const float* __restrict__ bout,
                                               float* __restrict__ out) {
    const int tid = threadIdx.x, w = tid >> 5, lane = tid & 31;
    const int g = lane >> 2, tig = lane & 3;
    const int m0 = blockIdx.y*128 + (w >> 2)*64;
    const int n0 = blockIdx.x*128 + (w & 3)*32;

    float c[4][4][4] = {};
    gemm_warp_64x32_p((const uint4*)g_ahi, (const uint4*)g_alo,
                      (const uint4*)g_w2hi, (const uint4*)g_w2lo,
                      m0, n0, g, tig, c);

    #pragma unroll
    for (int mt = 0; mt < 4; mt++)
    #pragma unroll
    for (int nt = 0; nt < 4; nt++)
    #pragma unroll
    for (int half = 0; half < 2; half++) {
        int mg = m0 + mt*16 + g + half*8;
        int ng = n0 + nt*8 + 2*tig;
        float2 v = { c[mt][nt][half*2]   + bout[ng],
                     c[mt][nt][half*2+1] + bout[ng+1] };
        *(float2*)(out + (size_t)mg*DIM_ + ng) = v;
    }
}

// ---------------- launch ---------------------------------------------------------
extern "C" void kernel_launch(void* const* d_in, const int* in_sizes, int n_in,
                              void* d_out, int out_size) {
    const float* x         = (const float*)d_in[0];
    const float* spd       = (const float*)d_in[1];
    const float* head_mask = (const float*)d_in[2];
    const float* W_qkv     = (const float*)d_in[3];
    const float* W_out     = (const float*)d_in[4];
    const float* b_out     = (const float*)d_in[5];
    float* out = (float*)d_out;

    __nv_bfloat16 *w1h, *w1l, *w2h, *w2l;
    cudaGetSymbolAddress((void**)&w1h, g_w1hi); cudaGetSymbolAddress((void**)&w1l, g_w1lo);
    cudaGetSymbolAddress((void**)&w2h, g_w2hi); cudaGetSymbolAddress((void**)&w2l, g_w2lo);

    k_split_x<<<MROWS/8, 256>>>(x);
    k_split_w<<<dim3(48, 8), 256>>>(W_qkv, 3*INNER_, w1h, w1l);
    k_split_w<<<dim3(16, 8), 256>>>(W_out, DIM_,     w2h, w2l);

    qkv_mma<<<dim3(12, 64), 256>>>();

    size_t smem = (size_t)(32*SD_STRIDE + 64)*sizeof(float);
    cudaFuncSetAttribute(attn_mma, cudaFuncAttributeMaxDynamicSharedMemorySize, (int)smem);
    attn_mma<<<dim3(N_/32, H_, B_), 512, smem>>>(spd, head_mask);

    out_mma<<<dim3(4, 64), 256>>>(b_out, out);
}

// round 13
// speedup vs baseline: 1.1480x; 1.0831x over previous
#include <cuda_runtime.h>
#include <cuda_bf16.h>
#include <cuda_fp16.h>
#include <math.h>
#include <stdint.h>

#define B_     8
#define N_     1024
#define DIM_   512
#define H_     8
#define DH_    64
#define INNER_ 512
#define MROWS  (B_*N_)
#define SCALE_ 0.125f
#define EPS_   1e-12f
#define SD_STRIDE 1028

// Word permutation within 32-word (64 k-element) blocks:
//   natural o = ks*8 + s*4 + tig   ->   stored p = tig*8 + ks*2 + s
__device__ __forceinline__ int permw(int o)   { return (o&3)*8 + (o>>3)*2 + ((o>>2)&1); }
__device__ __forceinline__ int invperm(int w) { return ((w>>1)&3)*8 + (w&1)*4 + (w>>3); }

// ---------------- scratch -----------------------------------------------------
__device__ __align__(256) __nv_bfloat16 g_xhi[MROWS*DIM_],     g_xlo[MROWS*DIM_];
__device__ __align__(256) __nv_bfloat16 g_w1hi[3*INNER_*DIM_], g_w1lo[3*INNER_*DIM_];
__device__ __align__(256) __half        g_w2hi[DIM_*INNER_],   g_w2lo[DIM_*INNER_];   // fp16 split
__device__ __align__(256) __nv_bfloat16 g_qhi[B_*H_*N_*DH_],   g_qlo[B_*H_*N_*DH_];
__device__ __align__(256) __nv_bfloat16 g_khi[B_*H_*N_*DH_],   g_klo[B_*H_*N_*DH_];
__device__ __align__(256) __half        g_vthi[B_*H_*DH_*N_],  g_vtlo[B_*H_*DH_*N_];  // fp16 split
__device__ __align__(256) __half        g_af[MROWS*INNER_];                            // fp16 single

// ---------------- helpers ------------------------------------------------------
__device__ __forceinline__ void mma_bf16(float* c, const uint32_t* a, uint32_t b0, uint32_t b1) {
    asm volatile("mma.sync.aligned.m16n8k16.row.col.f32.bf16.bf16.f32 "
        "{%0,%1,%2,%3}, {%4,%5,%6,%7}, {%8,%9}, {%0,%1,%2,%3};"
        : "+f"(c[0]), "+f"(c[1]), "+f"(c[2]), "+f"(c[3])
        : "r"(a[0]), "r"(a[1]), "r"(a[2]), "r"(a[3]), "r"(b0), "r"(b1));
}
__device__ __forceinline__ void mma_f16(float* c, const uint32_t* a, uint32_t b0, uint32_t b1) {
    asm volatile("mma.sync.aligned.m16n8k16.row.col.f32.f16.f16.f32 "
        "{%0,%1,%2,%3}, {%4,%5,%6,%7}, {%8,%9}, {%0,%1,%2,%3};"
        : "+f"(c[0]), "+f"(c[1]), "+f"(c[2]), "+f"(c[3])
        : "r"(a[0]), "r"(a[1]), "r"(a[2]), "r"(a[3]), "r"(b0), "r"(b1));
}

__device__ __forceinline__ void split2(float x, float y, uint32_t& h, uint32_t& l) {
    uint32_t hh;
    asm("cvt.rn.bf16x2.f32 %0, %1, %2;" : "=r"(hh) : "f"(y), "f"(x));
    float hx = __uint_as_float(hh << 16);
    float hy = __uint_as_float(hh & 0xFFFF0000u);
    uint32_t ll;
    asm("cvt.rn.bf16x2.f32 %0, %1, %2;" : "=r"(ll) : "f"(y - hy), "f"(x - hx));
    h = hh; l = ll;
}
__device__ __forceinline__ void split1(float x, __nv_bfloat16& h, __nv_bfloat16& l) {
    h = __float2bfloat16_rn(x);
    l = __float2bfloat16_rn(x - __bfloat162float(h));
}
__device__ __forceinline__ void split1h(float x, __half& h, __half& l) {
    h = __float2half_rn(x);
    l = __float2half_rn(x - __half2float(h));
}
__device__ __forceinline__ uint32_t pack2(__nv_bfloat16 e0, __nv_bfloat16 e1) {
    return ((uint32_t)__bfloat16_as_ushort(e1) << 16) | __bfloat16_as_ushort(e0);
}
__device__ __forceinline__ uint32_t pack2h(__half e0, __half e1) {
    return ((uint32_t)__half_as_ushort(e1) << 16) | __half_as_ushort(e0);
}

// ---------------- conversion kernels -------------------------------------------
__global__ void k_split_x(const float* __restrict__ in) {
    int row = blockIdx.x*8 + (threadIdx.x >> 5);
    int lane = threadIdx.x & 31;
    const float* src = in + (size_t)row*DIM_;
    uint32_t* dh = (uint32_t*)g_xhi + (size_t)row*256;
    uint32_t* dl = (uint32_t*)g_xlo + (size_t)row*256;
    #pragma unroll
    for (int j = 0; j < 8; j++) {
        int p = lane + 32*j;
        int o = (p & ~31) | invperm(p & 31);
        float2 v = *(const float2*)(src + 2*o);
        __nv_bfloat16 h0,l0,h1,l1; split1(v.x,h0,l0); split1(v.y,h1,l1);
        dh[p] = pack2(h0,h1);
        dl[p] = pack2(l0,l1);
    }
}

__global__ void k_split_w(const float* __restrict__ in, int W,
                          __nv_bfloat16* __restrict__ outh, __nv_bfloat16* __restrict__ outl) {
    __shared__ float s[64][33];
    int n0 = blockIdx.x*32, k0 = blockIdx.y*64;
    int t = threadIdx.x;
    int nn = t & 31, kk = t >> 5;
    #pragma unroll
    for (int i = 0; i < 8; i++)
        s[kk + 8*i][nn] = in[(size_t)(k0 + kk + 8*i)*W + n0 + nn];
    __syncthreads();
    int nl = t >> 3, wg = (t & 7)*4;
    uint32_t* oh = (uint32_t*)outh + (size_t)(n0+nl)*256 + blockIdx.y*32;
    uint32_t* ol = (uint32_t*)outl + (size_t)(n0+nl)*256 + blockIdx.y*32;
    #pragma unroll
    for (int j = 0; j < 4; j++) {
        int w = wg + j;
        int o = invperm(w);
        __nv_bfloat16 h0,l0,h1,l1;
        split1(s[2*o][nl],   h0, l0);
        split1(s[2*o+1][nl], h1, l1);
        oh[w] = pack2(h0,h1);
        ol[w] = pack2(l0,l1);
    }
}

// fp16 split version (for W_out)
__global__ void k_split_w_h(const float* __restrict__ in, int W,
                            __half* __restrict__ outh, __half* __restrict__ outl) {
    __shared__ float s[64][33];
    int n0 = blockIdx.x*32, k0 = blockIdx.y*64;
    int t = threadIdx.x;
    int nn = t & 31, kk = t >> 5;
    #pragma unroll
    for (int i = 0; i < 8; i++)
        s[kk + 8*i][nn] = in[(size_t)(k0 + kk + 8*i)*W + n0 + nn];
    __syncthreads();
    int nl = t >> 3, wg = (t & 7)*4;
    uint32_t* oh = (uint32_t*)outh + (size_t)(n0+nl)*256 + blockIdx.y*32;
    uint32_t* ol = (uint32_t*)outl + (size_t)(n0+nl)*256 + blockIdx.y*32;
    #pragma unroll
    for (int j = 0; j < 4; j++) {
        int w = wg + j;
        int o = invperm(w);
        __half h0,l0,h1,l1;
        split1h(s[2*o][nl],   h0, l0);
        split1h(s[2*o+1][nl], h1, l1);
        oh[w] = pack2h(h0,h1);
        ol[w] = pack2h(l0,l1);
    }
}

// ---------------- warp GEMM core: bf16 split 3-term (qkv) -----------------------
__device__ __forceinline__ void gemm_warp_64x32_p(
    const uint4* __restrict__ Ahi, const uint4* __restrict__ Alo,
    const uint4* __restrict__ Bhi, const uint4* __restrict__ Blo,
    int m_base, int n_base, int g, int tig, float c[4][4][4])
{
    for (int kb = 0; kb < 8; kb++) {
        uint32_t bh[4][8], bl[4][8];
        #pragma unroll
        for (int nt = 0; nt < 4; nt++) {
            const uint4* p = Bhi + (size_t)(n_base + nt*8 + g)*64 + kb*8 + tig*2;
            uint4 f0 = p[0], f1 = p[1];
            bh[nt][0]=f0.x; bh[nt][1]=f0.y; bh[nt][2]=f0.z; bh[nt][3]=f0.w;
            bh[nt][4]=f1.x; bh[nt][5]=f1.y; bh[nt][6]=f1.z; bh[nt][7]=f1.w;
            const uint4* q = Blo + (size_t)(n_base + nt*8 + g)*64 + kb*8 + tig*2;
            uint4 g0 = q[0], g1 = q[1];
            bl[nt][0]=g0.x; bl[nt][1]=g0.y; bl[nt][2]=g0.z; bl[nt][3]=g0.w;
            bl[nt][4]=g1.x; bl[nt][5]=g1.y; bl[nt][6]=g1.z; bl[nt][7]=g1.w;
        }
        #pragma unroll
        for (int mt = 0; mt < 4; mt++) {
            const uint4* pr = Ahi + (size_t)(m_base + mt*16 + g)*64 + kb*8 + tig*2;
            uint4 F0 = pr[0],     F1 = pr[1];
            uint4 S0 = pr[8*64],  S1 = pr[8*64 + 1];
            const uint4* ql = Alo + (size_t)(m_base + mt*16 + g)*64 + kb*8 + tig*2;
            uint4 G0 = ql[0],     G1 = ql[1];
            uint4 T0 = ql[8*64],  T1 = ql[8*64 + 1];
            uint32_t ah[4][4] = {
                {F0.x,S0.x,F0.y,S0.y},{F0.z,S0.z,F0.w,S0.w},
                {F1.x,S1.x,F1.y,S1.y},{F1.z,S1.z,F1.w,S1.w}};
            uint32_t al[4][4] = {
                {G0.x,T0.x,G0.y,T0.y},{G0.z,T0.z,G0.w,T0.w},
                {G1.x,T1.x,G1.y,T1.y},{G1.z,T1.z,G1.w,T1.w}};
            #pragma unroll
            for (int ks = 0; ks < 4; ks++)
                #pragma unroll
                for (int nt = 0; nt < 4; nt++) {
                    mma_bf16(c[mt][nt], ah[ks], bh[nt][ks*2], bh[nt][ks*2+1]);
                    mma_bf16(c[mt][nt], ah[ks], bl[nt][ks*2], bl[nt][ks*2+1]);
                    mma_bf16(c[mt][nt], al[ks], bh[nt][ks*2], bh[nt][ks*2+1]);
                }
        }
    }
}

// ---------------- warp GEMM core: fp16 A-single / B-split 2-term (out) ----------
__device__ __forceinline__ void gemm_warp_64x32_h(
    const uint4* __restrict__ Af,
    const uint4* __restrict__ Bhi, const uint4* __restrict__ Blo,
    int m_base, int n_base, int g, int tig, float c[4][4][4])
{
    for (int kb = 0; kb < 8; kb++) {
        uint32_t bh[4][8], bl[4][8];
        #pragma unroll
        for (int nt = 0; nt < 4; nt++) {
            const uint4* p = Bhi + (size_t)(n_base + nt*8 + g)*64 + kb*8 + tig*2;
            uint4 f0 = p[0], f1 = p[1];
            bh[nt][0]=f0.x; bh[nt][1]=f0.y; bh[nt][2]=f0.z; bh[nt][3]=f0.w;
            bh[nt][4]=f1.x; bh[nt][5]=f1.y; bh[nt][6]=f1.z; bh[nt][7]=f1.w;
            const uint4* q = Blo + (size_t)(n_base + nt*8 + g)*64 + kb*8 + tig*2;
            uint4 g0 = q[0], g1 = q[1];
            bl[nt][0]=g0.x; bl[nt][1]=g0.y; bl[nt][2]=g0.z; bl[nt][3]=g0.w;
            bl[nt][4]=g1.x; bl[nt][5]=g1.y; bl[nt][6]=g1.z; bl[nt][7]=g1.w;
        }
        #pragma unroll
        for (int mt = 0; mt < 4; mt++) {
            const uint4* pr = Af + (size_t)(m_base + mt*16 + g)*64 + kb*8 + tig*2;
            uint4 F0 = pr[0],     F1 = pr[1];
            uint4 S0 = pr[8*64],  S1 = pr[8*64 + 1];
            uint32_t ah[4][4] = {
                {F0.x,S0.x,F0.y,S0.y},{F0.z,S0.z,F0.w,S0.w},
                {F1.x,S1.x,F1.y,S1.y},{F1.z,S1.z,F1.w,S1.w}};
            #pragma unroll
            for (int ks = 0; ks < 4; ks++)
                #pragma unroll
                for (int nt = 0; nt < 4; nt++) {
                    mma_f16(c[mt][nt], ah[ks], bh[nt][ks*2], bh[nt][ks*2+1]);
                    mma_f16(c[mt][nt], ah[ks], bl[nt][ks*2], bl[nt][ks*2+1]);
                }
        }
    }
}

// ---------------- kernel 1: qkv projection (R8 config; V stored fp16 split) -----
__global__ void __launch_bounds__(256) qkv_mma() {
    const int tid = threadIdx.x, w = tid >> 5, lane = tid & 31;
    const int g = lane >> 2, tig = lane & 3;
    const int m0 = blockIdx.y*128 + (w >> 2)*64;
    const int n0 = blockIdx.x*128 + (w & 3)*32;

    float c[4][4][4] = {};
    gemm_warp_64x32_p((const uint4*)g_xhi, (const uint4*)g_xlo,
                      (const uint4*)g_w1hi, (const uint4*)g_w1lo,
                      m0, n0, g, tig, c);

    #pragma unroll
    for (int mt = 0; mt < 4; mt++)
    #pragma unroll
    for (int nt = 0; nt < 4; nt++)
    #pragma unroll
    for (int half = 0; half < 2; half++) {
        int mg = m0 + mt*16 + g + half*8;
        int bb = mg >> 10, nn = mg & 1023;
        int ng = n0 + nt*8 + 2*tig;
        int sec = ng >> 9;
        int cc  = ng & 511;
        int hh  = cc >> 6, dd = cc & 63;
        float xv = c[mt][nt][half*2], yv = c[mt][nt][half*2+1];
        if (sec < 2) {
            uint32_t h, l; split2(xv, yv, h, l);
            int pw = permw(dd >> 1);
            size_t widx = (((size_t)bb*H_ + hh)*N_ + nn)*32 + pw;
            if (sec == 0) { ((uint32_t*)g_qhi)[widx] = h; ((uint32_t*)g_qlo)[widx] = l; }
            else          { ((uint32_t*)g_khi)[widx] = h; ((uint32_t*)g_klo)[widx] = l; }
        } else {
            __half h0,l0,h1,l1; split1h(xv,h0,l0); split1h(yv,h1,l1);
            int o = nn >> 1, hb = nn & 1;
            int pe = ((o & ~31) | permw(o & 31))*2 + hb;
            size_t base = (((size_t)bb*H_ + hh)*DH_ + dd)*N_;
            g_vthi[base + pe] = h0;       g_vtlo[base + pe] = l0;
            g_vthi[base + N_ + pe] = h1;  g_vtlo[base + N_ + pe] = l1;
        }
    }
}

// ---------------- kernel 2: fused attention (fp16 probs, 2-term attn@V) ---------
__global__ void __launch_bounds__(512) attn_mma(const float* __restrict__ spd,
                                                const float* __restrict__ head_mask) {
    extern __shared__ float sD[];
    float* sStat = sD + 32*SD_STRIDE;
    const int tid = threadIdx.x, w = tid >> 5, lane = tid & 31;
    const int g = lane >> 2, tig = lane & 3;
    const int bb = blockIdx.z, hh = blockIdx.y, row0 = blockIdx.x*32;
    const int mw = w & 1, nw = w >> 1;
    const int mrow = mw*16 + g;

    if (tid < 64) sStat[tid] = 0.f;
    __syncthreads();

    const uint4* Khi4 = (const uint4*)g_khi + (size_t)(bb*H_+hh)*N_*8;
    const uint4* Klo4 = (const uint4*)g_klo + (size_t)(bb*H_+hh)*N_*8;

    // ---- phase 1: dots = (Q K^T) * SCALE into sD + fused norm partials ----
    uint32_t ah[4][4], al[4][4];
    {
        const uint4* qh = (const uint4*)g_qhi + ((size_t)(bb*H_+hh)*N_ + row0 + mrow)*8 + tig*2;
        const uint4* ql = (const uint4*)g_qlo + ((size_t)(bb*H_+hh)*N_ + row0 + mrow)*8 + tig*2;
        uint4 F0 = qh[0],    F1 = qh[1];
        uint4 S0 = qh[8*8],  S1 = qh[8*8+1];
        uint4 G0 = ql[0],    G1 = ql[1];
        uint4 T0 = ql[8*8],  T1 = ql[8*8+1];
        ah[0][0]=F0.x; ah[0][1]=S0.x; ah[0][2]=F0.y; ah[0][3]=S0.y;
        ah[1][0]=F0.z; ah[1][1]=S0.z; ah[1][2]=F0.w; ah[1][3]=S0.w;
        ah[2][0]=F1.x; ah[2][1]=S1.x; ah[2][2]=F1.y; ah[2][3]=S1.y;
        ah[3][0]=F1.z; ah[3][1]=S1.z; ah[3][2]=F1.w; ah[3][3]=S1.w;
        al[0][0]=G0.x; al[0][1]=T0.x; al[0][2]=G0.y; al[0][3]=T0.y;
        al[1][0]=G0.z; al[1][1]=T0.z; al[1][2]=G0.w; al[1][3]=T0.w;
        al[2][0]=G1.x; al[2][1]=T1.x; al[2][2]=G1.y; al[2][3]=T1.y;
        al[3][0]=G1.z; al[3][1]=T1.z; al[3][2]=G1.w; al[3][3]=T1.w;
    }
    const float* sp0 = spd + ((size_t)bb*N_ + row0 + mrow)*N_;
    const float* sp1 = sp0 + 8*N_;
    float d2a = 0.f, p2a = 0.f, d2b = 0.f, p2b = 0.f;

    #pragma unroll 2
    for (int nt = 0; nt < 16; nt++) {
        const int n0 = nw*128 + nt*8;
        const uint4* ph = Khi4 + (size_t)(n0+g)*8 + tig*2;
        const uint4* pl = Klo4 + (size_t)(n0+g)*8 + tig*2;
        uint4 F0 = ph[0], F1 = ph[1];
        uint4 G0 = pl[0], G1 = pl[1];
        uint32_t bhw[8] = {F0.x,F0.y,F0.z,F0.w,F1.x,F1.y,F1.z,F1.w};
        uint32_t blw[8] = {G0.x,G0.y,G0.z,G0.w,G1.x,G1.y,G1.z,G1.w};
        float c[4] = {0.f,0.f,0.f,0.f};
        #pragma unroll
        for (int ks = 0; ks < 4; ks++) {
            mma_bf16(c, ah[ks], bhw[ks*2], bhw[ks*2+1]);
            mma_bf16(c, ah[ks], blw[ks*2], blw[ks*2+1]);
            mma_bf16(c, al[ks], bhw[ks*2], bhw[ks*2+1]);
        }
        float2 v0 = { c[0]*SCALE_, c[1]*SCALE_ };
        float2 v1 = { c[2]*SCALE_, c[3]*SCALE_ };
        *(float2*)&sD[(size_t)mrow*SD_STRIDE + n0 + 2*tig]     = v0;
        *(float2*)&sD[(size_t)(mrow+8)*SD_STRIDE + n0 + 2*tig] = v1;
        float2 s0 = *(const float2*)&sp0[n0 + 2*tig];
        float2 s1 = *(const float2*)&sp1[n0 + 2*tig];
        d2a += v0.x*v0.x + v0.y*v0.y;
        p2a += (v0.x*s0.x)*(v0.x*s0.x) + (v0.y*s0.y)*(v0.y*s0.y);
        d2b += v1.x*v1.x + v1.y*v1.y;
        p2b += (v1.x*s1.x)*(v1.x*s1.x) + (v1.y*s1.y)*(v1.y*s1.y);
    }
    #pragma unroll
    for (int o = 1; o <= 2; o <<= 1) {
        d2a += __shfl_xor_sync(0xffffffffu, d2a, o);
        p2a += __shfl_xor_sync(0xffffffffu, p2a, o);
        d2b += __shfl_xor_sync(0xffffffffu, d2b, o);
        p2b += __shfl_xor_sync(0xffffffffu, p2b, o);
    }
    if      (tig == 0) atomicAdd(&sStat[mrow*2 + 0],     d2a);
    else if (tig == 1) atomicAdd(&sStat[mrow*2 + 1],     p2a);
    else if (tig == 2) atomicAdd(&sStat[(mrow+8)*2 + 0], d2b);
    else               atomicAdd(&sStat[(mrow+8)*2 + 1], p2b);
    __syncthreads();

    // ---- phase 2: exp (no max-sub) in regs, sum, repack SINGLE fp16 ----
    float msum = 0.f;
    #pragma unroll
    for (int i = 0; i < H_; i++) msum += head_mask[i];
    const float scale_m = head_mask[hh] * (float)H_ / msum;
    const int pl = permw(lane);

    #pragma unroll
    for (int rr = 0; rr < 2; rr++) {
        const int r = w*2 + rr, rg = row0 + r;
        float* drow = sD + (size_t)r*SD_STRIDE;
        const float* srow = spd + ((size_t)bb*N_ + rg)*N_;
        const float rnorm = sqrtf(sStat[2*r]) / fmaxf(sqrtf(sStat[2*r+1]), EPS_);

        float vb[32];
        float s = 0.f;
        #pragma unroll
        for (int i = 0; i < 16; i++) {
            float2 dp = *(const float2*)&drow[2*lane + 64*i];
            float2 sp = *(const float2*)&srow[2*lane + 64*i];
            float e0 = __expf(fmaf(dp.x*sp.x, rnorm, dp.x));
            float e1 = __expf(fmaf(dp.y*sp.y, rnorm, dp.y));
            vb[2*i] = e0; vb[2*i+1] = e1;
            s += e0 + e1;
        }
        #pragma unroll
        for (int o = 16; o > 0; o >>= 1) s += __shfl_xor_sync(0xffffffffu, s, o);
        const float inv = scale_m / s;

        uint32_t* dw = (uint32_t*)drow;
        #pragma unroll
        for (int i = 0; i < 16; i++) {
            __half h0 = __float2half_rn(vb[2*i]*inv);
            __half h1 = __float2half_rn(vb[2*i+1]*inv);
            dw[i*32 + pl] = pack2h(h0, h1);
        }
    }
    __syncthreads();

    // ---- phase 3: O = attn @ V (fp16 probs single x fp16 V split, 2 MMAs) ----
    const uint4* Vhi4 = (const uint4*)g_vthi + (size_t)(bb*H_+hh)*DH_*128;
    const uint4* Vlo4 = (const uint4*)g_vtlo + (size_t)(bb*H_+hh)*DH_*128;
    const int dh0 = nw*8;
    float oc[4] = {0.f,0.f,0.f,0.f};
    const uint4* r0 = (const uint4*)(sD + (size_t)mrow*SD_STRIDE);
    const uint4* r1 = (const uint4*)(sD + (size_t)(mrow+8)*SD_STRIDE);

    #pragma unroll 2
    for (int kb = 0; kb < 16; kb++) {
        const int ob = kb*8 + tig*2;
        uint4 F0 = r0[ob], F1 = r0[ob+1];
        uint4 H0 = r1[ob], H1 = r1[ob+1];
        uint32_t a4[4][4] = {
            {F0.x,H0.x,F0.y,H0.y},{F0.z,H0.z,F0.w,H0.w},
            {F1.x,H1.x,F1.y,H1.y},{F1.z,H1.z,F1.w,H1.w}};
        const uint4* ph = Vhi4 + (size_t)(dh0 + g)*128 + ob;
        const uint4* pv = Vlo4 + (size_t)(dh0 + g)*128 + ob;
        uint4 P0 = ph[0], P1 = ph[1];
        uint4 Q0 = pv[0], Q1 = pv[1];
        uint32_t bhw[8] = {P0.x,P0.y,P0.z,P0.w,P1.x,P1.y,P1.z,P1.w};
        uint32_t blw[8] = {Q0.x,Q0.y,Q0.z,Q0.w,Q1.x,Q1.y,Q1.z,Q1.w};
        #pragma unroll
        for (int ks = 0; ks < 4; ks++) {
            mma_f16(oc, a4[ks], bhw[ks*2], bhw[ks*2+1]);
            mma_f16(oc, a4[ks], blw[ks*2], blw[ks*2+1]);
        }
    }

    #pragma unroll
    for (int half = 0; half < 2; half++) {
        int rg  = row0 + mw*16 + g + half*8;
        size_t mg = (size_t)bb*N_ + rg;
        int rcol = dh0 + 2*tig;
        __half h0 = __float2half_rn(oc[half*2]);
        __half h1 = __float2half_rn(oc[half*2+1]);
        int pw = hh*32 + permw(rcol >> 1);
        ((uint32_t*)g_af)[mg*256 + pw] = pack2h(h0, h1);
    }
}

// ---------------- kernel 3: output projection (fp16 2-term) ---------------------
__global__ void __launch_bounds__(256) out_mma(const float* __restrict__ bout,
                                               float* __restrict__ out) {
    const int tid = threadIdx.x, w = tid >> 5, lane = tid & 31;
    const int g = lane >> 2, tig = lane & 3;
    const int m0 = blockIdx.y*128 + (w >> 2)*64;
    const int n0 = blockIdx.x*128 + (w & 3)*32;

    float c[4][4][4] = {};
    gemm_warp_64x32_h((const uint4*)g_af,
                      (const uint4*)g_w2hi, (const uint4*)g_w2lo,
                      m0, n0, g, tig, c);

    #pragma unroll
    for (int mt = 0; mt < 4; mt++)
    #pragma unroll
    for (int nt = 0; nt < 4; nt++)
    #pragma unroll
    for (int half = 0; half < 2; half++) {
        int mg = m0 + mt*16 + g + half*8;
        int ng = n0 + nt*8 + 2*tig;
        float2 v = { c[mt][nt][half*2]   + bout[ng],
                     c[mt][nt][half*2+1] + bout[ng+1] };
        *(float2*)(out + (size_t)mg*DIM_ + ng) = v;
    }
}

// ---------------- launch ---------------------------------------------------------
extern "C" void kernel_launch(void* const* d_in, const int* in_sizes, int n_in,
                              void* d_out, int out_size) {
    const float* x         = (const float*)d_in[0];
    const float* spd       = (const float*)d_in[1];
    const float* head_mask = (const float*)d_in[2];
    const float* W_qkv     = (const float*)d_in[3];
    const float* W_out     = (const float*)d_in[4];
    const float* b_out     = (const float*)d_in[5];
    float* out = (float*)d_out;

    __nv_bfloat16 *w1h, *w1l;
    __half *w2h, *w2l;
    cudaGetSymbolAddress((void**)&w1h, g_w1hi); cudaGetSymbolAddress((void**)&w1l, g_w1lo);
    cudaGetSymbolAddress((void**)&w2h, g_w2hi); cudaGetSymbolAddress((void**)&w2l, g_w2lo);

    k_split_x<<<MROWS/8, 256>>>(x);
    k_split_w<<<dim3(48, 8), 256>>>(W_qkv, 3*INNER_, w1h, w1l);
    k_split_w_h<<<dim3(16, 8), 256>>>(W_out, DIM_, w2h, w2l);

    qkv_mma<<<dim3(12, 64), 256>>>();

    size_t smem = (size_t)(32*SD_STRIDE + 64)*sizeof(float);
    cudaFuncSetAttribute(attn_mma, cudaFuncAttributeMaxDynamicSharedMemorySize, (int)smem);
    attn_mma<<<dim3(N_/32, H_, B_), 512, smem>>>(spd, head_mask);

    out_mma<<<dim3(4, 64), 256>>>(b_out, out);
}

// round 14
// speedup vs baseline: 1.2408x; 1.0808x over previous
#include <cuda_runtime.h>
#include <cuda_bf16.h>
#include <cuda_fp16.h>
#include <math.h>
#include <stdint.h>

#define B_     8
#define N_     1024
#define DIM_   512
#define H_     8
#define DH_    64
#define INNER_ 512
#define MROWS  (B_*N_)
#define SCALE_ 0.125f
#define EPS_   1e-12f
#define SD_STRIDE 1028

// Word permutation within 32-word (64 k-element) blocks:
//   natural o = ks*8 + s*4 + tig   ->   stored p = tig*8 + ks*2 + s
__device__ __forceinline__ int permw(int o)   { return (o&3)*8 + (o>>3)*2 + ((o>>2)&1); }
__device__ __forceinline__ int invperm(int w) { return ((w>>1)&3)*8 + (w&1)*4 + (w>>3); }

// ---------------- scratch -----------------------------------------------------
__device__ __align__(256) __nv_bfloat16 g_xhi[MROWS*DIM_],     g_xlo[MROWS*DIM_];
__device__ __align__(256) __nv_bfloat16 g_w1hi[3*INNER_*DIM_], g_w1lo[3*INNER_*DIM_];
__device__ __align__(256) __half        g_w2hi[DIM_*INNER_],   g_w2lo[DIM_*INNER_];   // fp16 split
__device__ __align__(256) __nv_bfloat16 g_qhi[B_*H_*N_*DH_],   g_qlo[B_*H_*N_*DH_];
__device__ __align__(256) __nv_bfloat16 g_khi[B_*H_*N_*DH_],   g_klo[B_*H_*N_*DH_];
__device__ __align__(256) __half        g_vtf[B_*H_*DH_*N_];                           // fp16 single
__device__ __align__(256) __half        g_af[MROWS*INNER_];                            // fp16 single

// ---------------- helpers ------------------------------------------------------
__device__ __forceinline__ void mma_bf16(float* c, const uint32_t* a, uint32_t b0, uint32_t b1) {
    asm volatile("mma.sync.aligned.m16n8k16.row.col.f32.bf16.bf16.f32 "
        "{%0,%1,%2,%3}, {%4,%5,%6,%7}, {%8,%9}, {%0,%1,%2,%3};"
        : "+f"(c[0]), "+f"(c[1]), "+f"(c[2]), "+f"(c[3])
        : "r"(a[0]), "r"(a[1]), "r"(a[2]), "r"(a[3]), "r"(b0), "r"(b1));
}
__device__ __forceinline__ void mma_f16(float* c, const uint32_t* a, uint32_t b0, uint32_t b1) {
    asm volatile("mma.sync.aligned.m16n8k16.row.col.f32.f16.f16.f32 "
        "{%0,%1,%2,%3}, {%4,%5,%6,%7}, {%8,%9}, {%0,%1,%2,%3};"
        : "+f"(c[0]), "+f"(c[1]), "+f"(c[2]), "+f"(c[3])
        : "r"(a[0]), "r"(a[1]), "r"(a[2]), "r"(a[3]), "r"(b0), "r"(b1));
}

__device__ __forceinline__ void split2(float x, float y, uint32_t& h, uint32_t& l) {
    uint32_t hh;
    asm("cvt.rn.bf16x2.f32 %0, %1, %2;" : "=r"(hh) : "f"(y), "f"(x));
    float hx = __uint_as_float(hh << 16);
    float hy = __uint_as_float(hh & 0xFFFF0000u);
    uint32_t ll;
    asm("cvt.rn.bf16x2.f32 %0, %1, %2;" : "=r"(ll) : "f"(y - hy), "f"(x - hx));
    h = hh; l = ll;
}
__device__ __forceinline__ void split1(float x, __nv_bfloat16& h, __nv_bfloat16& l) {
    h = __float2bfloat16_rn(x);
    l = __float2bfloat16_rn(x - __bfloat162float(h));
}
__device__ __forceinline__ void split1h(float x, __half& h, __half& l) {
    h = __float2half_rn(x);
    l = __float2half_rn(x - __half2float(h));
}
__device__ __forceinline__ uint32_t pack2(__nv_bfloat16 e0, __nv_bfloat16 e1) {
    return ((uint32_t)__bfloat16_as_ushort(e1) << 16) | __bfloat16_as_ushort(e0);
}
__device__ __forceinline__ uint32_t pack2h(__half e0, __half e1) {
    return ((uint32_t)__half_as_ushort(e1) << 16) | __half_as_ushort(e0);
}

// ---------------- conversion kernels -------------------------------------------
__global__ void k_split_x(const float* __restrict__ in) {
    int row = blockIdx.x*8 + (threadIdx.x >> 5);
    int lane = threadIdx.x & 31;
    const float* src = in + (size_t)row*DIM_;
    uint32_t* dh = (uint32_t*)g_xhi + (size_t)row*256;
    uint32_t* dl = (uint32_t*)g_xlo + (size_t)row*256;
    #pragma unroll
    for (int j = 0; j < 8; j++) {
        int p = lane + 32*j;
        int o = (p & ~31) | invperm(p & 31);
        float2 v = *(const float2*)(src + 2*o);
        __nv_bfloat16 h0,l0,h1,l1; split1(v.x,h0,l0); split1(v.y,h1,l1);
        dh[p] = pack2(h0,h1);
        dl[p] = pack2(l0,l1);
    }
}

__global__ void k_split_w(const float* __restrict__ in, int W,
                          __nv_bfloat16* __restrict__ outh, __nv_bfloat16* __restrict__ outl) {
    __shared__ float s[64][33];
    int n0 = blockIdx.x*32, k0 = blockIdx.y*64;
    int t = threadIdx.x;
    int nn = t & 31, kk = t >> 5;
    #pragma unroll
    for (int i = 0; i < 8; i++)
        s[kk + 8*i][nn] = in[(size_t)(k0 + kk + 8*i)*W + n0 + nn];
    __syncthreads();
    int nl = t >> 3, wg = (t & 7)*4;
    uint32_t* oh = (uint32_t*)outh + (size_t)(n0+nl)*256 + blockIdx.y*32;
    uint32_t* ol = (uint32_t*)outl + (size_t)(n0+nl)*256 + blockIdx.y*32;
    #pragma unroll
    for (int j = 0; j < 4; j++) {
        int w = wg + j;
        int o = invperm(w);
        __nv_bfloat16 h0,l0,h1,l1;
        split1(s[2*o][nl],   h0, l0);
        split1(s[2*o+1][nl], h1, l1);
        oh[w] = pack2(h0,h1);
        ol[w] = pack2(l0,l1);
    }
}

// fp16 split version (for W_out)
__global__ void k_split_w_h(const float* __restrict__ in, int W,
                            __half* __restrict__ outh, __half* __restrict__ outl) {
    __shared__ float s[64][33];
    int n0 = blockIdx.x*32, k0 = blockIdx.y*64;
    int t = threadIdx.x;
    int nn = t & 31, kk = t >> 5;
    #pragma unroll
    for (int i = 0; i < 8; i++)
        s[kk + 8*i][nn] = in[(size_t)(k0 + kk + 8*i)*W + n0 + nn];
    __syncthreads();
    int nl = t >> 3, wg = (t & 7)*4;
    uint32_t* oh = (uint32_t*)outh + (size_t)(n0+nl)*256 + blockIdx.y*32;
    uint32_t* ol = (uint32_t*)outl + (size_t)(n0+nl)*256 + blockIdx.y*32;
    #pragma unroll
    for (int j = 0; j < 4; j++) {
        int w = wg + j;
        int o = invperm(w);
        __half h0,l0,h1,l1;
        split1h(s[2*o][nl],   h0, l0);
        split1h(s[2*o+1][nl], h1, l1);
        oh[w] = pack2h(h0,h1);
        ol[w] = pack2h(l0,l1);
    }
}

// ---------------- warp GEMM core: bf16 split 3-term (qkv) -----------------------
__device__ __forceinline__ void gemm_warp_64x32_p(
    const uint4* __restrict__ Ahi, const uint4* __restrict__ Alo,
    const uint4* __restrict__ Bhi, const uint4* __restrict__ Blo,
    int m_base, int n_base, int g, int tig, float c[4][4][4])
{
    for (int kb = 0; kb < 8; kb++) {
        uint32_t bh[4][8], bl[4][8];
        #pragma unroll
        for (int nt = 0; nt < 4; nt++) {
            const uint4* p = Bhi + (size_t)(n_base + nt*8 + g)*64 + kb*8 + tig*2;
            uint4 f0 = p[0], f1 = p[1];
            bh[nt][0]=f0.x; bh[nt][1]=f0.y; bh[nt][2]=f0.z; bh[nt][3]=f0.w;
            bh[nt][4]=f1.x; bh[nt][5]=f1.y; bh[nt][6]=f1.z; bh[nt][7]=f1.w;
            const uint4* q = Blo + (size_t)(n_base + nt*8 + g)*64 + kb*8 + tig*2;
            uint4 g0 = q[0], g1 = q[1];
            bl[nt][0]=g0.x; bl[nt][1]=g0.y; bl[nt][2]=g0.z; bl[nt][3]=g0.w;
            bl[nt][4]=g1.x; bl[nt][5]=g1.y; bl[nt][6]=g1.z; bl[nt][7]=g1.w;
        }
        #pragma unroll
        for (int mt = 0; mt < 4; mt++) {
            const uint4* pr = Ahi + (size_t)(m_base + mt*16 + g)*64 + kb*8 + tig*2;
            uint4 F0 = pr[0],     F1 = pr[1];
            uint4 S0 = pr[8*64],  S1 = pr[8*64 + 1];
            const uint4* ql = Alo + (size_t)(m_base + mt*16 + g)*64 + kb*8 + tig*2;
            uint4 G0 = ql[0],     G1 = ql[1];
            uint4 T0 = ql[8*64],  T1 = ql[8*64 + 1];
            uint32_t ah[4][4] = {
                {F0.x,S0.x,F0.y,S0.y},{F0.z,S0.z,F0.w,S0.w},
                {F1.x,S1.x,F1.y,S1.y},{F1.z,S1.z,F1.w,S1.w}};
            uint32_t al[4][4] = {
                {G0.x,T0.x,G0.y,T0.y},{G0.z,T0.z,G0.w,T0.w},
                {G1.x,T1.x,G1.y,T1.y},{G1.z,T1.z,G1.w,T1.w}};
            #pragma unroll
            for (int ks = 0; ks < 4; ks++)
                #pragma unroll
                for (int nt = 0; nt < 4; nt++) {
                    mma_bf16(c[mt][nt], ah[ks], bh[nt][ks*2], bh[nt][ks*2+1]);
                    mma_bf16(c[mt][nt], ah[ks], bl[nt][ks*2], bl[nt][ks*2+1]);
                    mma_bf16(c[mt][nt], al[ks], bh[nt][ks*2], bh[nt][ks*2+1]);
                }
        }
    }
}

// ---------------- warp GEMM core: fp16 A-single / B-split 2-term (out) ----------
__device__ __forceinline__ void gemm_warp_64x32_h(
    const uint4* __restrict__ Af,
    const uint4* __restrict__ Bhi, const uint4* __restrict__ Blo,
    int m_base, int n_base, int g, int tig, float c[4][4][4])
{
    for (int kb = 0; kb < 8; kb++) {
        uint32_t bh[4][8], bl[4][8];
        #pragma unroll
        for (int nt = 0; nt < 4; nt++) {
            const uint4* p = Bhi + (size_t)(n_base + nt*8 + g)*64 + kb*8 + tig*2;
            uint4 f0 = p[0], f1 = p[1];
            bh[nt][0]=f0.x; bh[nt][1]=f0.y; bh[nt][2]=f0.z; bh[nt][3]=f0.w;
            bh[nt][4]=f1.x; bh[nt][5]=f1.y; bh[nt][6]=f1.z; bh[nt][7]=f1.w;
            const uint4* q = Blo + (size_t)(n_base + nt*8 + g)*64 + kb*8 + tig*2;
            uint4 g0 = q[0], g1 = q[1];
            bl[nt][0]=g0.x; bl[nt][1]=g0.y; bl[nt][2]=g0.z; bl[nt][3]=g0.w;
            bl[nt][4]=g1.x; bl[nt][5]=g1.y; bl[nt][6]=g1.z; bl[nt][7]=g1.w;
        }
        #pragma unroll
        for (int mt = 0; mt < 4; mt++) {
            const uint4* pr = Af + (size_t)(m_base + mt*16 + g)*64 + kb*8 + tig*2;
            uint4 F0 = pr[0],     F1 = pr[1];
            uint4 S0 = pr[8*64],  S1 = pr[8*64 + 1];
            uint32_t ah[4][4] = {
                {F0.x,S0.x,F0.y,S0.y},{F0.z,S0.z,F0.w,S0.w},
                {F1.x,S1.x,F1.y,S1.y},{F1.z,S1.z,F1.w,S1.w}};
            #pragma unroll
            for (int ks = 0; ks < 4; ks++)
                #pragma unroll
                for (int nt = 0; nt < 4; nt++) {
                    mma_f16(c[mt][nt], ah[ks], bh[nt][ks*2], bh[nt][ks*2+1]);
                    mma_f16(c[mt][nt], ah[ks], bl[nt][ks*2], bl[nt][ks*2+1]);
                }
        }
    }
}

// ---------------- kernel 1: qkv projection (V stored single fp16) ---------------
__global__ void __launch_bounds__(256) qkv_mma() {
    const int tid = threadIdx.x, w = tid >> 5, lane = tid & 31;
    const int g = lane >> 2, tig = lane & 3;
    const int m0 = blockIdx.y*128 + (w >> 2)*64;
    const int n0 = blockIdx.x*128 + (w & 3)*32;

    float c[4][4][4] = {};
    gemm_warp_64x32_p((const uint4*)g_xhi, (const uint4*)g_xlo,
                      (const uint4*)g_w1hi, (const uint4*)g_w1lo,
                      m0, n0, g, tig, c);

    #pragma unroll
    for (int mt = 0; mt < 4; mt++)
    #pragma unroll
    for (int nt = 0; nt < 4; nt++)
    #pragma unroll
    for (int half = 0; half < 2; half++) {
        int mg = m0 + mt*16 + g + half*8;
        int bb = mg >> 10, nn = mg & 1023;
        int ng = n0 + nt*8 + 2*tig;
        int sec = ng >> 9;
        int cc  = ng & 511;
        int hh  = cc >> 6, dd = cc & 63;
        float xv = c[mt][nt][half*2], yv = c[mt][nt][half*2+1];
        if (sec < 2) {
            uint32_t h, l; split2(xv, yv, h, l);
            int pw = permw(dd >> 1);
            size_t widx = (((size_t)bb*H_ + hh)*N_ + nn)*32 + pw;
            if (sec == 0) { ((uint32_t*)g_qhi)[widx] = h; ((uint32_t*)g_qlo)[widx] = l; }
            else          { ((uint32_t*)g_khi)[widx] = h; ((uint32_t*)g_klo)[widx] = l; }
        } else {
            int o = nn >> 1, hb = nn & 1;
            int pe = ((o & ~31) | permw(o & 31))*2 + hb;
            size_t base = (((size_t)bb*H_ + hh)*DH_ + dd)*N_;
            g_vtf[base + pe]      = __float2half_rn(xv);
            g_vtf[base + N_ + pe] = __float2half_rn(yv);
        }
    }
}

// ---------------- kernel 2: fused attention (fp16 probs x fp16 V, 1 MMA) --------
__global__ void __launch_bounds__(512) attn_mma(const float* __restrict__ spd,
                                                const float* __restrict__ head_mask) {
    extern __shared__ float sD[];
    float* sStat = sD + 32*SD_STRIDE;
    const int tid = threadIdx.x, w = tid >> 5, lane = tid & 31;
    const int g = lane >> 2, tig = lane & 3;
    const int bb = blockIdx.z, hh = blockIdx.y, row0 = blockIdx.x*32;
    const int mw = w & 1, nw = w >> 1;
    const int mrow = mw*16 + g;

    if (tid < 64) sStat[tid] = 0.f;
    __syncthreads();

    const uint4* Khi4 = (const uint4*)g_khi + (size_t)(bb*H_+hh)*N_*8;
    const uint4* Klo4 = (const uint4*)g_klo + (size_t)(bb*H_+hh)*N_*8;

    // ---- phase 1: dots = (Q K^T) * SCALE into sD + fused norm partials ----
    uint32_t ah[4][4], al[4][4];
    {
        const uint4* qh = (const uint4*)g_qhi + ((size_t)(bb*H_+hh)*N_ + row0 + mrow)*8 + tig*2;
        const uint4* ql = (const uint4*)g_qlo + ((size_t)(bb*H_+hh)*N_ + row0 + mrow)*8 + tig*2;
        uint4 F0 = qh[0],    F1 = qh[1];
        uint4 S0 = qh[8*8],  S1 = qh[8*8+1];
        uint4 G0 = ql[0],    G1 = ql[1];
        uint4 T0 = ql[8*8],  T1 = ql[8*8+1];
        ah[0][0]=F0.x; ah[0][1]=S0.x; ah[0][2]=F0.y; ah[0][3]=S0.y;
        ah[1][0]=F0.z; ah[1][1]=S0.z; ah[1][2]=F0.w; ah[1][3]=S0.w;
        ah[2][0]=F1.x; ah[2][1]=S1.x; ah[2][2]=F1.y; ah[2][3]=S1.y;
        ah[3][0]=F1.z; ah[3][1]=S1.z; ah[3][2]=F1.w; ah[3][3]=S1.w;
        al[0][0]=G0.x; al[0][1]=T0.x; al[0][2]=G0.y; al[0][3]=T0.y;
        al[1][0]=G0.z; al[1][1]=T0.z; al[1][2]=G0.w; al[1][3]=T0.w;
        al[2][0]=G1.x; al[2][1]=T1.x; al[2][2]=G1.y; al[2][3]=T1.y;
        al[3][0]=G1.z; al[3][1]=T1.z; al[3][2]=G1.w; al[3][3]=T1.w;
    }
    const float* sp0 = spd + ((size_t)bb*N_ + row0 + mrow)*N_;
    const float* sp1 = sp0 + 8*N_;
    float d2a = 0.f, p2a = 0.f, d2b = 0.f, p2b = 0.f;

    #pragma unroll 2
    for (int nt = 0; nt < 16; nt++) {
        const int n0 = nw*128 + nt*8;
        const uint4* ph = Khi4 + (size_t)(n0+g)*8 + tig*2;
        const uint4* pl = Klo4 + (size_t)(n0+g)*8 + tig*2;
        uint4 F0 = ph[0], F1 = ph[1];
        uint4 G0 = pl[0], G1 = pl[1];
        uint32_t bhw[8] = {F0.x,F0.y,F0.z,F0.w,F1.x,F1.y,F1.z,F1.w};
        uint32_t blw[8] = {G0.x,G0.y,G0.z,G0.w,G1.x,G1.y,G1.z,G1.w};
        float c[4] = {0.f,0.f,0.f,0.f};
        #pragma unroll
        for (int ks = 0; ks < 4; ks++) {
            mma_bf16(c, ah[ks], bhw[ks*2], bhw[ks*2+1]);
            mma_bf16(c, ah[ks], blw[ks*2], blw[ks*2+1]);
            mma_bf16(c, al[ks], bhw[ks*2], bhw[ks*2+1]);
        }
        float2 v0 = { c[0]*SCALE_, c[1]*SCALE_ };
        float2 v1 = { c[2]*SCALE_, c[3]*SCALE_ };
        *(float2*)&sD[(size_t)mrow*SD_STRIDE + n0 + 2*tig]     = v0;
        *(float2*)&sD[(size_t)(mrow+8)*SD_STRIDE + n0 + 2*tig] = v1;
        float2 s0 = *(const float2*)&sp0[n0 + 2*tig];
        float2 s1 = *(const float2*)&sp1[n0 + 2*tig];
        d2a += v0.x*v0.x + v0.y*v0.y;
        p2a += (v0.x*s0.x)*(v0.x*s0.x) + (v0.y*s0.y)*(v0.y*s0.y);
        d2b += v1.x*v1.x + v1.y*v1.y;
        p2b += (v1.x*s1.x)*(v1.x*s1.x) + (v1.y*s1.y)*(v1.y*s1.y);
    }
    #pragma unroll
    for (int o = 1; o <= 2; o <<= 1) {
        d2a += __shfl_xor_sync(0xffffffffu, d2a, o);
        p2a += __shfl_xor_sync(0xffffffffu, p2a, o);
        d2b += __shfl_xor_sync(0xffffffffu, d2b, o);
        p2b += __shfl_xor_sync(0xffffffffu, p2b, o);
    }
    if      (tig == 0) atomicAdd(&sStat[mrow*2 + 0],     d2a);
    else if (tig == 1) atomicAdd(&sStat[mrow*2 + 1],     p2a);
    else if (tig == 2) atomicAdd(&sStat[(mrow+8)*2 + 0], d2b);
    else               atomicAdd(&sStat[(mrow+8)*2 + 1], p2b);
    __syncthreads();

    // ---- phase 2: exp (no max-sub) in regs, sum, repack SINGLE fp16 ----
    float msum = 0.f;
    #pragma unroll
    for (int i = 0; i < H_; i++) msum += head_mask[i];
    const float scale_m = head_mask[hh] * (float)H_ / msum;
    const int pl = permw(lane);

    #pragma unroll
    for (int rr = 0; rr < 2; rr++) {
        const int r = w*2 + rr, rg = row0 + r;
        float* drow = sD + (size_t)r*SD_STRIDE;
        const float* srow = spd + ((size_t)bb*N_ + rg)*N_;
        const float rnorm = sqrtf(sStat[2*r]) / fmaxf(sqrtf(sStat[2*r+1]), EPS_);

        float vb[32];
        float s = 0.f;
        #pragma unroll
        for (int i = 0; i < 16; i++) {
            float2 dp = *(const float2*)&drow[2*lane + 64*i];
            float2 sp = *(const float2*)&srow[2*lane + 64*i];
            float e0 = __expf(fmaf(dp.x*sp.x, rnorm, dp.x));
            float e1 = __expf(fmaf(dp.y*sp.y, rnorm, dp.y));
            vb[2*i] = e0; vb[2*i+1] = e1;
            s += e0 + e1;
        }
        #pragma unroll
        for (int o = 16; o > 0; o >>= 1) s += __shfl_xor_sync(0xffffffffu, s, o);
        const float inv = scale_m / s;

        uint32_t* dw = (uint32_t*)drow;
        #pragma unroll
        for (int i = 0; i < 16; i++) {
            __half h0 = __float2half_rn(vb[2*i]*inv);
            __half h1 = __float2half_rn(vb[2*i+1]*inv);
            dw[i*32 + pl] = pack2h(h0, h1);
        }
    }
    __syncthreads();

    // ---- phase 3: O = attn @ V (fp16 x fp16, single MMA per k-step) ----
    const uint4* Vf4 = (const uint4*)g_vtf + (size_t)(bb*H_+hh)*DH_*128;
    const int dh0 = nw*8;
    float oc[4] = {0.f,0.f,0.f,0.f};
    const uint4* r0 = (const uint4*)(sD + (size_t)mrow*SD_STRIDE);
    const uint4* r1 = (const uint4*)(sD + (size_t)(mrow+8)*SD_STRIDE);

    #pragma unroll 2
    for (int kb = 0; kb < 16; kb++) {
        const int ob = kb*8 + tig*2;
        uint4 F0 = r0[ob], F1 = r0[ob+1];
        uint4 H0 = r1[ob], H1 = r1[ob+1];
        uint32_t a4[4][4] = {
            {F0.x,H0.x,F0.y,H0.y},{F0.z,H0.z,F0.w,H0.w},
            {F1.x,H1.x,F1.y,H1.y},{F1.z,H1.z,F1.w,H1.w}};
        const uint4* ph = Vf4 + (size_t)(dh0 + g)*128 + ob;
        uint4 P0 = ph[0], P1 = ph[1];
        uint32_t bhw[8] = {P0.x,P0.y,P0.z,P0.w,P1.x,P1.y,P1.z,P1.w};
        #pragma unroll
        for (int ks = 0; ks < 4; ks++)
            mma_f16(oc, a4[ks], bhw[ks*2], bhw[ks*2+1]);
    }

    #pragma unroll
    for (int half = 0; half < 2; half++) {
        int rg  = row0 + mw*16 + g + half*8;
        size_t mg = (size_t)bb*N_ + rg;
        int rcol = dh0 + 2*tig;
        __half h0 = __float2half_rn(oc[half*2]);
        __half h1 = __float2half_rn(oc[half*2+1]);
        int pw = hh*32 + permw(rcol >> 1);
        ((uint32_t*)g_af)[mg*256 + pw] = pack2h(h0, h1);
    }
}

// ---------------- kernel 3: output projection (fp16 2-term) ---------------------
__global__ void __launch_bounds__(256) out_mma(const float* __restrict__ bout,
                                               float* __restrict__ out) {
    const int tid = threadIdx.x, w = tid >> 5, lane = tid & 31;
    const int g = lane >> 2, tig = lane & 3;
    const int m0 = blockIdx.y*128 + (w >> 2)*64;
    const int n0 = blockIdx.x*128 + (w & 3)*32;

    float c[4][4][4] = {};
    gemm_warp_64x32_h((const uint4*)g_af,
                      (const uint4*)g_w2hi, (const uint4*)g_w2lo,
                      m0, n0, g, tig, c);

    #pragma unroll
    for (int mt = 0; mt < 4; mt++)
    #pragma unroll
    for (int nt = 0; nt < 4; nt++)
    #pragma unroll
    for (int half = 0; half < 2; half++) {
        int mg = m0 + mt*16 + g + half*8;
        int ng = n0 + nt*8 + 2*tig;
        float2 v = { c[mt][nt][half*2]   + bout[ng],
                     c[mt][nt][half*2+1] + bout[ng+1] };
        *(float2*)(out + (size_t)mg*DIM_ + ng) = v;
    }
}

// ---------------- launch ---------------------------------------------------------
extern "C" void kernel_launch(void* const* d_in, const int* in_sizes, int n_in,
                              void* d_out, int out_size) {
    const float* x         = (const float*)d_in[0];
    const float* spd       = (const float*)d_in[1];
    const float* head_mask = (const float*)d_in[2];
    const float* W_qkv     = (const float*)d_in[3];
    const float* W_out     = (const float*)d_in[4];
    const float* b_out     = (const float*)d_in[5];
    float* out = (float*)d_out;

    __nv_bfloat16 *w1h, *w1l;
    __half *w2h, *w2l;
    cudaGetSymbolAddress((void**)&w1h, g_w1hi); cudaGetSymbolAddress((void**)&w1l, g_w1lo);
    cudaGetSymbolAddress((void**)&w2h, g_w2hi); cudaGetSymbolAddress((void**)&w2l, g_w2lo);

    k_split_x<<<MROWS/8, 256>>>(x);
    k_split_w<<<dim3(48, 8), 256>>>(W_qkv, 3*INNER_, w1h, w1l);
    k_split_w_h<<<dim3(16, 8), 256>>>(W_out, DIM_, w2h, w2l);

    qkv_mma<<<dim3(12, 64), 256>>>();

    size_t smem = (size_t)(32*SD_STRIDE + 64)*sizeof(float);
    cudaFuncSetAttribute(attn_mma, cudaFuncAttributeMaxDynamicSharedMemorySize, (int)smem);
    attn_mma<<<dim3(N_/32, H_, B_), 512, smem>>>(spd, head_mask);

    out_mma<<<dim3(4, 64), 256>>>(b_out, out);
}

// round 15
// speedup vs baseline: 1.2685x; 1.0223x over previous
#include <cuda_runtime.h>
#include <cuda_bf16.h>
#include <cuda_fp16.h>
#include <math.h>
#include <stdint.h>

#define B_     8
#define N_     1024
#define DIM_   512
#define H_     8
#define DH_    64
#define INNER_ 512
#define MROWS  (B_*N_)
#define SCALE_ 0.125f
#define EPS_   1e-12f
#define SD_STRIDE 1028

// Word permutation within 32-word (64 k-element) blocks:
//   natural o = ks*8 + s*4 + tig   ->   stored p = tig*8 + ks*2 + s
__device__ __forceinline__ int permw(int o)   { return (o&3)*8 + (o>>3)*2 + ((o>>2)&1); }
__device__ __forceinline__ int invperm(int w) { return ((w>>1)&3)*8 + (w&1)*4 + (w>>3); }

// ---------------- scratch -----------------------------------------------------
__device__ __align__(256) __nv_bfloat16 g_xhi[MROWS*DIM_],     g_xlo[MROWS*DIM_];
__device__ __align__(256) __nv_bfloat16 g_w1hi[3*INNER_*DIM_], g_w1lo[3*INNER_*DIM_];
__device__ __align__(256) __half        g_w2hi[DIM_*INNER_],   g_w2lo[DIM_*INNER_];   // fp16 split
__device__ __align__(256) __nv_bfloat16 g_qhi[B_*H_*N_*DH_],   g_qlo[B_*H_*N_*DH_];
__device__ __align__(256) __nv_bfloat16 g_khi[B_*H_*N_*DH_],   g_klo[B_*H_*N_*DH_];
__device__ __align__(256) __half        g_vtf[B_*H_*DH_*N_];                           // fp16 single
__device__ __align__(256) __half        g_af[MROWS*INNER_];                            // fp16 single

// ---------------- helpers ------------------------------------------------------
__device__ __forceinline__ void mma_bf16(float* c, const uint32_t* a, uint32_t b0, uint32_t b1) {
    asm volatile("mma.sync.aligned.m16n8k16.row.col.f32.bf16.bf16.f32 "
        "{%0,%1,%2,%3}, {%4,%5,%6,%7}, {%8,%9}, {%0,%1,%2,%3};"
        : "+f"(c[0]), "+f"(c[1]), "+f"(c[2]), "+f"(c[3])
        : "r"(a[0]), "r"(a[1]), "r"(a[2]), "r"(a[3]), "r"(b0), "r"(b1));
}
__device__ __forceinline__ void mma_f16(float* c, const uint32_t* a, uint32_t b0, uint32_t b1) {
    asm volatile("mma.sync.aligned.m16n8k16.row.col.f32.f16.f16.f32 "
        "{%0,%1,%2,%3}, {%4,%5,%6,%7}, {%8,%9}, {%0,%1,%2,%3};"
        : "+f"(c[0]), "+f"(c[1]), "+f"(c[2]), "+f"(c[3])
        : "r"(a[0]), "r"(a[1]), "r"(a[2]), "r"(a[3]), "r"(b0), "r"(b1));
}

__device__ __forceinline__ void split2(float x, float y, uint32_t& h, uint32_t& l) {
    uint32_t hh;
    asm("cvt.rn.bf16x2.f32 %0, %1, %2;" : "=r"(hh) : "f"(y), "f"(x));
    float hx = __uint_as_float(hh << 16);
    float hy = __uint_as_float(hh & 0xFFFF0000u);
    uint32_t ll;
    asm("cvt.rn.bf16x2.f32 %0, %1, %2;" : "=r"(ll) : "f"(y - hy), "f"(x - hx));
    h = hh; l = ll;
}
__device__ __forceinline__ void split1(float x, __nv_bfloat16& h, __nv_bfloat16& l) {
    h = __float2bfloat16_rn(x);
    l = __float2bfloat16_rn(x - __bfloat162float(h));
}
__device__ __forceinline__ void split1h(float x, __half& h, __half& l) {
    h = __float2half_rn(x);
    l = __float2half_rn(x - __half2float(h));
}
__device__ __forceinline__ uint32_t pack2(__nv_bfloat16 e0, __nv_bfloat16 e1) {
    return ((uint32_t)__bfloat16_as_ushort(e1) << 16) | __bfloat16_as_ushort(e0);
}
__device__ __forceinline__ uint32_t pack2h(__half e0, __half e1) {
    return ((uint32_t)__half_as_ushort(e1) << 16) | __half_as_ushort(e0);
}

// ---------------- conversion kernels -------------------------------------------
__global__ void k_split_x(const float* __restrict__ in) {
    int row = blockIdx.x*8 + (threadIdx.x >> 5);
    int lane = threadIdx.x & 31;
    const float* src = in + (size_t)row*DIM_;
    uint32_t* dh = (uint32_t*)g_xhi + (size_t)row*256;
    uint32_t* dl = (uint32_t*)g_xlo + (size_t)row*256;
    #pragma unroll
    for (int j = 0; j < 8; j++) {
        int p = lane + 32*j;
        int o = (p & ~31) | invperm(p & 31);
        float2 v = *(const float2*)(src + 2*o);
        __nv_bfloat16 h0,l0,h1,l1; split1(v.x,h0,l0); split1(v.y,h1,l1);
        dh[p] = pack2(h0,h1);
        dl[p] = pack2(l0,l1);
    }
}

__global__ void k_split_w(const float* __restrict__ in, int W,
                          __nv_bfloat16* __restrict__ outh, __nv_bfloat16* __restrict__ outl) {
    __shared__ float s[64][33];
    int n0 = blockIdx.x*32, k0 = blockIdx.y*64;
    int t = threadIdx.x;
    int nn = t & 31, kk = t >> 5;
    #pragma unroll
    for (int i = 0; i < 8; i++)
        s[kk + 8*i][nn] = in[(size_t)(k0 + kk + 8*i)*W + n0 + nn];
    __syncthreads();
    int nl = t >> 3, wg = (t & 7)*4;
    uint32_t* oh = (uint32_t*)outh + (size_t)(n0+nl)*256 + blockIdx.y*32;
    uint32_t* ol = (uint32_t*)outl + (size_t)(n0+nl)*256 + blockIdx.y*32;
    #pragma unroll
    for (int j = 0; j < 4; j++) {
        int w = wg + j;
        int o = invperm(w);
        __nv_bfloat16 h0,l0,h1,l1;
        split1(s[2*o][nl],   h0, l0);
        split1(s[2*o+1][nl], h1, l1);
        oh[w] = pack2(h0,h1);
        ol[w] = pack2(l0,l1);
    }
}

// fp16 split version (for W_out)
__global__ void k_split_w_h(const float* __restrict__ in, int W,
                            __half* __restrict__ outh, __half* __restrict__ outl) {
    __shared__ float s[64][33];
    int n0 = blockIdx.x*32, k0 = blockIdx.y*64;
    int t = threadIdx.x;
    int nn = t & 31, kk = t >> 5;
    #pragma unroll
    for (int i = 0; i < 8; i++)
        s[kk + 8*i][nn] = in[(size_t)(k0 + kk + 8*i)*W + n0 + nn];
    __syncthreads();
    int nl = t >> 3, wg = (t & 7)*4;
    uint32_t* oh = (uint32_t*)outh + (size_t)(n0+nl)*256 + blockIdx.y*32;
    uint32_t* ol = (uint32_t*)outl + (size_t)(n0+nl)*256 + blockIdx.y*32;
    #pragma unroll
    for (int j = 0; j < 4; j++) {
        int w = wg + j;
        int o = invperm(w);
        __half h0,l0,h1,l1;
        split1h(s[2*o][nl],   h0, l0);
        split1h(s[2*o+1][nl], h1, l1);
        oh[w] = pack2h(h0,h1);
        ol[w] = pack2h(l0,l1);
    }
}

// ---------------- warp GEMM core: bf16 split 3-term (qkv) -----------------------
__device__ __forceinline__ void gemm_warp_64x32_p(
    const uint4* __restrict__ Ahi, const uint4* __restrict__ Alo,
    const uint4* __restrict__ Bhi, const uint4* __restrict__ Blo,
    int m_base, int n_base, int g, int tig, float c[4][4][4])
{
    for (int kb = 0; kb < 8; kb++) {
        uint32_t bh[4][8], bl[4][8];
        #pragma unroll
        for (int nt = 0; nt < 4; nt++) {
            const uint4* p = Bhi + (size_t)(n_base + nt*8 + g)*64 + kb*8 + tig*2;
            uint4 f0 = p[0], f1 = p[1];
            bh[nt][0]=f0.x; bh[nt][1]=f0.y; bh[nt][2]=f0.z; bh[nt][3]=f0.w;
            bh[nt][4]=f1.x; bh[nt][5]=f1.y; bh[nt][6]=f1.z; bh[nt][7]=f1.w;
            const uint4* q = Blo + (size_t)(n_base + nt*8 + g)*64 + kb*8 + tig*2;
            uint4 g0 = q[0], g1 = q[1];
            bl[nt][0]=g0.x; bl[nt][1]=g0.y; bl[nt][2]=g0.z; bl[nt][3]=g0.w;
            bl[nt][4]=g1.x; bl[nt][5]=g1.y; bl[nt][6]=g1.z; bl[nt][7]=g1.w;
        }
        #pragma unroll
        for (int mt = 0; mt < 4; mt++) {
            const uint4* pr = Ahi + (size_t)(m_base + mt*16 + g)*64 + kb*8 + tig*2;
            uint4 F0 = pr[0],     F1 = pr[1];
            uint4 S0 = pr[8*64],  S1 = pr[8*64 + 1];
            const uint4* ql = Alo + (size_t)(m_base + mt*16 + g)*64 + kb*8 + tig*2;
            uint4 G0 = ql[0],     G1 = ql[1];
            uint4 T0 = ql[8*64],  T1 = ql[8*64 + 1];
            uint32_t ah[4][4] = {
                {F0.x,S0.x,F0.y,S0.y},{F0.z,S0.z,F0.w,S0.w},
                {F1.x,S1.x,F1.y,S1.y},{F1.z,S1.z,F1.w,S1.w}};
            uint32_t al[4][4] = {
                {G0.x,T0.x,G0.y,T0.y},{G0.z,T0.z,G0.w,T0.w},
                {G1.x,T1.x,G1.y,T1.y},{G1.z,T1.z,G1.w,T1.w}};
            #pragma unroll
            for (int ks = 0; ks < 4; ks++)
                #pragma unroll
                for (int nt = 0; nt < 4; nt++) {
                    mma_bf16(c[mt][nt], ah[ks], bh[nt][ks*2], bh[nt][ks*2+1]);
                    mma_bf16(c[mt][nt], ah[ks], bl[nt][ks*2], bl[nt][ks*2+1]);
                    mma_bf16(c[mt][nt], al[ks], bh[nt][ks*2], bh[nt][ks*2+1]);
                }
        }
    }
}

// ---------------- warp GEMM core: fp16 A-single / B-split 2-term (out) ----------
__device__ __forceinline__ void gemm_warp_64x32_h(
    const uint4* __restrict__ Af,
    const uint4* __restrict__ Bhi, const uint4* __restrict__ Blo,
    int m_base, int n_base, int g, int tig, float c[4][4][4])
{
    for (int kb = 0; kb < 8; kb++) {
        uint32_t bh[4][8], bl[4][8];
        #pragma unroll
        for (int nt = 0; nt < 4; nt++) {
            const uint4* p = Bhi + (size_t)(n_base + nt*8 + g)*64 + kb*8 + tig*2;
            uint4 f0 = p[0], f1 = p[1];
            bh[nt][0]=f0.x; bh[nt][1]=f0.y; bh[nt][2]=f0.z; bh[nt][3]=f0.w;
            bh[nt][4]=f1.x; bh[nt][5]=f1.y; bh[nt][6]=f1.z; bh[nt][7]=f1.w;
            const uint4* q = Blo + (size_t)(n_base + nt*8 + g)*64 + kb*8 + tig*2;
            uint4 g0 = q[0], g1 = q[1];
            bl[nt][0]=g0.x; bl[nt][1]=g0.y; bl[nt][2]=g0.z; bl[nt][3]=g0.w;
            bl[nt][4]=g1.x; bl[nt][5]=g1.y; bl[nt][6]=g1.z; bl[nt][7]=g1.w;
        }
        #pragma unroll
        for (int mt = 0; mt < 4; mt++) {
            const uint4* pr = Af + (size_t)(m_base + mt*16 + g)*64 + kb*8 + tig*2;
            uint4 F0 = pr[0],     F1 = pr[1];
            uint4 S0 = pr[8*64],  S1 = pr[8*64 + 1];
            uint32_t ah[4][4] = {
                {F0.x,S0.x,F0.y,S0.y},{F0.z,S0.z,F0.w,S0.w},
                {F1.x,S1.x,F1.y,S1.y},{F1.z,S1.z,F1.w,S1.w}};
            #pragma unroll
            for (int ks = 0; ks < 4; ks++)
                #pragma unroll
                for (int nt = 0; nt < 4; nt++) {
                    mma_f16(c[mt][nt], ah[ks], bh[nt][ks*2], bh[nt][ks*2+1]);
                    mma_f16(c[mt][nt], ah[ks], bl[nt][ks*2], bl[nt][ks*2+1]);
                }
        }
    }
}

// ---------------- kernel 1: qkv projection (V stored single fp16) ---------------
__global__ void __launch_bounds__(256) qkv_mma() {
    const int tid = threadIdx.x, w = tid >> 5, lane = tid & 31;
    const int g = lane >> 2, tig = lane & 3;
    const int m0 = blockIdx.y*128 + (w >> 2)*64;
    const int n0 = blockIdx.x*128 + (w & 3)*32;

    float c[4][4][4] = {};
    gemm_warp_64x32_p((const uint4*)g_xhi, (const uint4*)g_xlo,
                      (const uint4*)g_w1hi, (const uint4*)g_w1lo,
                      m0, n0, g, tig, c);

    #pragma unroll
    for (int mt = 0; mt < 4; mt++)
    #pragma unroll
    for (int nt = 0; nt < 4; nt++)
    #pragma unroll
    for (int half = 0; half < 2; half++) {
        int mg = m0 + mt*16 + g + half*8;
        int bb = mg >> 10, nn = mg & 1023;
        int ng = n0 + nt*8 + 2*tig;
        int sec = ng >> 9;
        int cc  = ng & 511;
        int hh  = cc >> 6, dd = cc & 63;
        float xv = c[mt][nt][half*2], yv = c[mt][nt][half*2+1];
        if (sec < 2) {
            uint32_t h, l; split2(xv, yv, h, l);
            int pw = permw(dd >> 1);
            size_t widx = (((size_t)bb*H_ + hh)*N_ + nn)*32 + pw;
            if (sec == 0) { ((uint32_t*)g_qhi)[widx] = h; ((uint32_t*)g_qlo)[widx] = l; }
            else          { ((uint32_t*)g_khi)[widx] = h; ((uint32_t*)g_klo)[widx] = l; }
        } else {
            int o = nn >> 1, hb = nn & 1;
            int pe = ((o & ~31) | permw(o & 31))*2 + hb;
            size_t base = (((size_t)bb*H_ + hh)*DH_ + dd)*N_;
            g_vtf[base + pe]      = __float2half_rn(xv);
            g_vtf[base + N_ + pe] = __float2half_rn(yv);
        }
    }
}

// ---------------- kernel 2: fused attention (prefetched loads) ------------------
__global__ void __launch_bounds__(512) attn_mma(const float* __restrict__ spd,
                                                const float* __restrict__ head_mask) {
    extern __shared__ float sD[];
    float* sStat = sD + 32*SD_STRIDE;
    const int tid = threadIdx.x, w = tid >> 5, lane = tid & 31;
    const int g = lane >> 2, tig = lane & 3;
    const int bb = blockIdx.z, hh = blockIdx.y, row0 = blockIdx.x*32;
    const int mw = w & 1, nw = w >> 1;
    const int mrow = mw*16 + g;

    if (tid < 64) sStat[tid] = 0.f;
    __syncthreads();

    const uint4* Khi4 = (const uint4*)g_khi + (size_t)(bb*H_+hh)*N_*8;
    const uint4* Klo4 = (const uint4*)g_klo + (size_t)(bb*H_+hh)*N_*8;

    // ---- phase 1: dots = (Q K^T) * SCALE into sD + fused norm partials ----
    uint32_t ah[4][4], al[4][4];
    {
        const uint4* qh = (const uint4*)g_qhi + ((size_t)(bb*H_+hh)*N_ + row0 + mrow)*8 + tig*2;
        const uint4* ql = (const uint4*)g_qlo + ((size_t)(bb*H_+hh)*N_ + row0 + mrow)*8 + tig*2;
        uint4 F0 = qh[0],    F1 = qh[1];
        uint4 S0 = qh[8*8],  S1 = qh[8*8+1];
        uint4 G0 = ql[0],    G1 = ql[1];
        uint4 T0 = ql[8*8],  T1 = ql[8*8+1];
        ah[0][0]=F0.x; ah[0][1]=S0.x; ah[0][2]=F0.y; ah[0][3]=S0.y;
        ah[1][0]=F0.z; ah[1][1]=S0.z; ah[1][2]=F0.w; ah[1][3]=S0.w;
        ah[2][0]=F1.x; ah[2][1]=S1.x; ah[2][2]=F1.y; ah[2][3]=S1.y;
        ah[3][0]=F1.z; ah[3][1]=S1.z; ah[3][2]=F1.w; ah[3][3]=S1.w;
        al[0][0]=G0.x; al[0][1]=T0.x; al[0][2]=G0.y; al[0][3]=T0.y;
        al[1][0]=G0.z; al[1][1]=T0.z; al[1][2]=G0.w; al[1][3]=T0.w;
        al[2][0]=G1.x; al[2][1]=T1.x; al[2][2]=G1.y; al[2][3]=T1.y;
        al[3][0]=G1.z; al[3][1]=T1.z; al[3][2]=G1.w; al[3][3]=T1.w;
    }
    const float* sp0 = spd + ((size_t)bb*N_ + row0 + mrow)*N_;
    const float* sp1 = sp0 + 8*N_;
    float d2a = 0.f, p2a = 0.f, d2b = 0.f, p2b = 0.f;

    const int n0b = nw*128;
    // preload nt=0
    uint4 F0c, F1c, G0c, G1c;
    float2 s0c, s1c;
    {
        const uint4* ph = Khi4 + (size_t)(n0b+g)*8 + tig*2;
        const uint4* pl = Klo4 + (size_t)(n0b+g)*8 + tig*2;
        F0c = ph[0]; F1c = ph[1]; G0c = pl[0]; G1c = pl[1];
        s0c = *(const float2*)&sp0[n0b + 2*tig];
        s1c = *(const float2*)&sp1[n0b + 2*tig];
    }
    #pragma unroll 2
    for (int nt = 0; nt < 16; nt++) {
        const int n0 = n0b + nt*8;
        // prefetch nt+1
        uint4 F0n = {}, F1n = {}, G0n = {}, G1n = {};
        float2 s0n = {}, s1n = {};
        if (nt < 15) {
            const int n1 = n0 + 8;
            const uint4* ph = Khi4 + (size_t)(n1+g)*8 + tig*2;
            const uint4* pl = Klo4 + (size_t)(n1+g)*8 + tig*2;
            F0n = ph[0]; F1n = ph[1]; G0n = pl[0]; G1n = pl[1];
            s0n = *(const float2*)&sp0[n1 + 2*tig];
            s1n = *(const float2*)&sp1[n1 + 2*tig];
        }
        uint32_t bhw[8] = {F0c.x,F0c.y,F0c.z,F0c.w,F1c.x,F1c.y,F1c.z,F1c.w};
        uint32_t blw[8] = {G0c.x,G0c.y,G0c.z,G0c.w,G1c.x,G1c.y,G1c.z,G1c.w};
        float c[4] = {0.f,0.f,0.f,0.f};
        #pragma unroll
        for (int ks = 0; ks < 4; ks++) {
            mma_bf16(c, ah[ks], bhw[ks*2], bhw[ks*2+1]);
            mma_bf16(c, ah[ks], blw[ks*2], blw[ks*2+1]);
            mma_bf16(c, al[ks], bhw[ks*2], bhw[ks*2+1]);
        }
        float2 v0 = { c[0]*SCALE_, c[1]*SCALE_ };
        float2 v1 = { c[2]*SCALE_, c[3]*SCALE_ };
        *(float2*)&sD[(size_t)mrow*SD_STRIDE + n0 + 2*tig]     = v0;
        *(float2*)&sD[(size_t)(mrow+8)*SD_STRIDE + n0 + 2*tig] = v1;
        d2a += v0.x*v0.x + v0.y*v0.y;
        p2a += (v0.x*s0c.x)*(v0.x*s0c.x) + (v0.y*s0c.y)*(v0.y*s0c.y);
        d2b += v1.x*v1.x + v1.y*v1.y;
        p2b += (v1.x*s1c.x)*(v1.x*s1c.x) + (v1.y*s1c.y)*(v1.y*s1c.y);
        F0c = F0n; F1c = F1n; G0c = G0n; G1c = G1n;
        s0c = s0n; s1c = s1n;
    }
    #pragma unroll
    for (int o = 1; o <= 2; o <<= 1) {
        d2a += __shfl_xor_sync(0xffffffffu, d2a, o);
        p2a += __shfl_xor_sync(0xffffffffu, p2a, o);
        d2b += __shfl_xor_sync(0xffffffffu, d2b, o);
        p2b += __shfl_xor_sync(0xffffffffu, p2b, o);
    }
    if      (tig == 0) atomicAdd(&sStat[mrow*2 + 0],     d2a);
    else if (tig == 1) atomicAdd(&sStat[mrow*2 + 1],     p2a);
    else if (tig == 2) atomicAdd(&sStat[(mrow+8)*2 + 0], d2b);
    else               atomicAdd(&sStat[(mrow+8)*2 + 1], p2b);
    __syncthreads();

    // ---- phase 2: exp (no max-sub) in regs, sum, repack SINGLE fp16 ----
    float msum = 0.f;
    #pragma unroll
    for (int i = 0; i < H_; i++) msum += head_mask[i];
    const float scale_m = head_mask[hh] * (float)H_ / msum;
    const int pl = permw(lane);

    #pragma unroll
    for (int rr = 0; rr < 2; rr++) {
        const int r = w*2 + rr, rg = row0 + r;
        float* drow = sD + (size_t)r*SD_STRIDE;
        const float* srow = spd + ((size_t)bb*N_ + rg)*N_;
        const float rnorm = sqrtf(sStat[2*r]) / fmaxf(sqrtf(sStat[2*r+1]), EPS_);

        float vb[32];
        float s = 0.f;
        #pragma unroll
        for (int i = 0; i < 16; i++) {
            float2 dp = *(const float2*)&drow[2*lane + 64*i];
            float2 sp = *(const float2*)&srow[2*lane + 64*i];
            float e0 = __expf(fmaf(dp.x*sp.x, rnorm, dp.x));
            float e1 = __expf(fmaf(dp.y*sp.y, rnorm, dp.y));
            vb[2*i] = e0; vb[2*i+1] = e1;
            s += e0 + e1;
        }
        #pragma unroll
        for (int o = 16; o > 0; o >>= 1) s += __shfl_xor_sync(0xffffffffu, s, o);
        const float inv = scale_m / s;

        uint32_t* dw = (uint32_t*)drow;
        #pragma unroll
        for (int i = 0; i < 16; i++) {
            __half h0 = __float2half_rn(vb[2*i]*inv);
            __half h1 = __float2half_rn(vb[2*i+1]*inv);
            dw[i*32 + pl] = pack2h(h0, h1);
        }
    }
    __syncthreads();

    // ---- phase 3: O = attn @ V (fp16 x fp16, single MMA; V prefetched) ----
    const uint4* Vf4 = (const uint4*)g_vtf + (size_t)(bb*H_+hh)*DH_*128;
    const int dh0 = nw*8;
    float oc[4] = {0.f,0.f,0.f,0.f};
    const uint4* r0 = (const uint4*)(sD + (size_t)mrow*SD_STRIDE);
    const uint4* r1 = (const uint4*)(sD + (size_t)(mrow+8)*SD_STRIDE);
    const uint4* Vrow = Vf4 + (size_t)(dh0 + g)*128;

    uint4 P0c = Vrow[tig*2], P1c = Vrow[tig*2 + 1];
    #pragma unroll 2
    for (int kb = 0; kb < 16; kb++) {
        uint4 P0n = {}, P1n = {};
        if (kb < 15) {
            P0n = Vrow[(kb+1)*8 + tig*2];
            P1n = Vrow[(kb+1)*8 + tig*2 + 1];
        }
        const int ob = kb*8 + tig*2;
        uint4 F0 = r0[ob], F1 = r0[ob+1];
        uint4 H0 = r1[ob], H1 = r1[ob+1];
        uint32_t a4[4][4] = {
            {F0.x,H0.x,F0.y,H0.y},{F0.z,H0.z,F0.w,H0.w},
            {F1.x,H1.x,F1.y,H1.y},{F1.z,H1.z,F1.w,H1.w}};
        uint32_t bhw[8] = {P0c.x,P0c.y,P0c.z,P0c.w,P1c.x,P1c.y,P1c.z,P1c.w};
        #pragma unroll
        for (int ks = 0; ks < 4; ks++)
            mma_f16(oc, a4[ks], bhw[ks*2], bhw[ks*2+1]);
        P0c = P0n; P1c = P1n;
    }

    #pragma unroll
    for (int half = 0; half < 2; half++) {
        int rg  = row0 + mw*16 + g + half*8;
        size_t mg = (size_t)bb*N_ + rg;
        int rcol = dh0 + 2*tig;
        __half h0 = __float2half_rn(oc[half*2]);
        __half h1 = __float2half_rn(oc[half*2+1]);
        int pw = hh*32 + permw(rcol >> 1);
        ((uint32_t*)g_af)[mg*256 + pw] = pack2h(h0, h1);
    }
}

// ---------------- kernel 3: output projection (fp16 2-term) ---------------------
__global__ void __launch_bounds__(256) out_mma(const float* __restrict__ bout,
                                               float* __restrict__ out) {
    const int tid = threadIdx.x, w = tid >> 5, lane = tid & 31;
    const int g = lane >> 2, tig = lane & 3;
    const int m0 = blockIdx.y*128 + (w >> 2)*64;
    const int n0 = blockIdx.x*128 + (w & 3)*32;

    float c[4][4][4] = {};
    gemm_warp_64x32_h((const uint4*)g_af,
                      (const uint4*)g_w2hi, (const uint4*)g_w2lo,
                      m0, n0, g, tig, c);

    #pragma unroll
    for (int mt = 0; mt < 4; mt++)
    #pragma unroll
    for (int nt = 0; nt < 4; nt++)
    #pragma unroll
    for (int half = 0; half < 2; half++) {
        int mg = m0 + mt*16 + g + half*8;
        int ng = n0 + nt*8 + 2*tig;
        float2 v = { c[mt][nt][half*2]   + bout[ng],
                     c[mt][nt][half*2+1] + bout[ng+1] };
        *(float2*)(out + (size_t)mg*DIM_ + ng) = v;
    }
}

// ---------------- launch ---------------------------------------------------------
extern "C" void kernel_launch(void* const* d_in, const int* in_sizes, int n_in,
                              void* d_out, int out_size) {
    const float* x         = (const float*)d_in[0];
    const float* spd       = (const float*)d_in[1];
    const float* head_mask = (const float*)d_in[2];
    const float* W_qkv     = (const float*)d_in[3];
    const float* W_out     = (const float*)d_in[4];
    const float* b_out     = (const float*)d_in[5];
    float* out = (float*)d_out;

    __nv_bfloat16 *w1h, *w1l;
    __half *w2h, *w2l;
    cudaGetSymbolAddress((void**)&w1h, g_w1hi); cudaGetSymbolAddress((void**)&w1l, g_w1lo);
    cudaGetSymbolAddress((void**)&w2h, g_w2hi); cudaGetSymbolAddress((void**)&w2l, g_w2lo);

    k_split_x<<<MROWS/8, 256>>>(x);
    k_split_w<<<dim3(48, 8), 256>>>(W_qkv, 3*INNER_, w1h, w1l);
    k_split_w_h<<<dim3(16, 8), 256>>>(W_out, DIM_, w2h, w2l);

    qkv_mma<<<dim3(12, 64), 256>>>();

    size_t smem = (size_t)(32*SD_STRIDE + 64)*sizeof(float);
    cudaFuncSetAttribute(attn_mma, cudaFuncAttributeMaxDynamicSharedMemorySize, (int)smem);
    attn_mma<<<dim3(N_/32, H_, B_), 512, smem>>>(spd, head_mask);

    out_mma<<<dim3(4, 64), 256>>>(b_out, out);
}